// round 14
// baseline (speedup 1.0000x reference)
#include <cuda_runtime.h>
#include <math.h>
#include <stdint.h>

#define BB 8
#define TT 96
#define NN 20000
#define PP 12
#define DD 32
#define CC 128
#define MM 64
#define GX 18   // gate0 grid.x (144 CTAs, 1/SM)
// 2 * 32^-0.25  (inv_sqrt_tau * d^-1/4)
#define SC 0.8408964152537145f
#define RATIO 0.125f
#define EPSF 1e-6f

typedef unsigned long long ull;

// ---- packed f32x2 helpers ----------------------------------------------------
__device__ __forceinline__ void ffma2(ull& d, ull a, ull b) {
    asm("fma.rn.f32x2 %0, %1, %2, %0;" : "+l"(d) : "l"(a), "l"(b));
}
__device__ __forceinline__ ull dupf(float v) {
    ull r; asm("mov.b64 %0, {%1, %1};" : "=l"(r) : "f"(v)); return r;
}
__device__ __forceinline__ float2 u2f(ull v) {
    float2 f; asm("mov.b64 {%0, %1}, %2;" : "=f"(f.x), "=f"(f.y) : "l"(v)); return f;
}

// ---- ordered-uint encoding for float atomicMax --------------------------------
__device__ __forceinline__ unsigned fenc(float f) {
    unsigned b = __float_as_uint(f);
    return (b & 0x80000000u) ? ~b : (b | 0x80000000u);
}
__device__ __forceinline__ float fdec(unsigned e) {
    unsigned b = (e & 0x80000000u) ? (e ^ 0x80000000u) : ~e;
    return __uint_as_float(b);
}

// ------------------------- static device scratch -----------------------------
__device__ float d_h[BB*NN*CC];
__device__ float d_xin[BB*NN*DD];
__device__ float d_ngi[NN*CC];
__device__ float d_ngo[NN*CC];
__device__ float d_bgi[BB*CC];
__device__ float d_bgo[BB*CC];
__device__ float d_phiq[BB*NN*MM];
__device__ float d_phik[BB*NN*MM];
__device__ float d_skip[BB*NN*PP];
__device__ float d_np1[NN*DD], d_np2[NN*DD];
__device__ float d_nd1[NN*MM], d_nd2[NN*MM];
__device__ unsigned d_colenc[MM];
__device__ float d_bp1[BB*DD], d_bp2[BB*DD];
__device__ float d_bd1[BB*MM], d_bd2[BB*MM];
__device__ float d_biasin[BB*DD];
__device__ float d_te[BB*DD], d_we[BB*DD];
__device__ float d_skipb[BB*PP];
__device__ float d_kv[3*BB*MM*CC];
__device__ float d_ksum[BB*MM];

// ------------------------- per-batch constants --------------------------------
__global__ __launch_bounds__(256) void k_batch(
    const float* __restrict__ x_mark, const float* __restrict__ time_tab,
    const float* __restrict__ week_tab,
    const float* __restrict__ w1_w, const float* __restrict__ w1_b,
    const float* __restrict__ w2_w, const float* __restrict__ w2_b,
    const float* __restrict__ input_w, const float* __restrict__ input_b,
    const float* __restrict__ proj, const float* __restrict__ reg_w,
    const float* __restrict__ in_w, const float* __restrict__ out_w)
{
    __shared__ float bp1s[BB*DD], bp2s[BB*DD];
    __shared__ float tesh[BB*DD], wesh[BB*DD];
    __shared__ int tods[BB], dows[BB];
    int tid = threadIdx.x;
    if (tid < MM) d_colenc[tid] = 0u;
    d_ksum[tid] = 0.f;
    d_ksum[256 + tid] = 0.f;
    if (tid < BB) {
        float v0 = x_mark[tid*TT*2 + (TT-1)*2 + 0];
        float v1 = x_mark[tid*TT*2 + (TT-1)*2 + 1];
        int ti = (int)(v0 * (float)TT); ti = ti < 0 ? 0 : (ti > TT-1 ? TT-1 : ti);
        int di = (int)(v1 * 7.0f);      di = di < 0 ? 0 : (di > 6 ? 6 : di);
        tods[tid] = ti; dows[tid] = di;
    }
    __syncthreads();
    int b = tid >> 5, c = tid & 31;
    float te = time_tab[tods[b]*DD + c];
    float we = week_tab[dows[b]*DD + c];
    d_te[b*DD+c] = te; d_we[b*DD+c] = we;
    tesh[b*DD+c] = te; wesh[b*DD+c] = we;

    float a1 = w1_b[c], a2 = w2_b[c];
    for (int g = 0; g < DD; g++) {
        float tg = time_tab[tods[b]*DD+g], wg = week_tab[dows[b]*DD+g];
        a1 += tg * w1_w[c*(3*DD) + DD + g] + wg * w1_w[c*(3*DD) + 2*DD + g];
        a2 += tg * w2_w[c*(3*DD) + DD + g] + wg * w2_w[c*(3*DD) + 2*DD + g];
    }
    a1 *= SC; a2 *= SC;
    d_bp1[b*DD+c] = a1; d_bp2[b*DD+c] = a2;
    bp1s[b*DD+c] = a1;  bp2s[b*DD+c] = a2;

    float bi = input_b[c];
    for (int t = 0; t < TT; t++) {
        bi += x_mark[b*TT*2 + t*2 + 0] * input_w[c*(3*TT) + TT + t]
            + x_mark[b*TT*2 + t*2 + 1] * input_w[c*(3*TT) + 2*TT + t];
    }
    d_biasin[b*DD+c] = bi;

    if (c < PP) {
        float s = 0.f;
        for (int g = 0; g < DD; g++)
            s += time_tab[tods[b]*DD+g] * reg_w[c*(2*CC) + 2*DD + g]
               + week_tab[dows[b]*DD+g] * reg_w[c*(2*CC) + 3*DD + g];
        d_skipb[b*PP + c] = s;
    }
    __syncthreads();
    for (int mm = c; mm < MM; mm += 32) {
        float s1 = 0.f, s2 = 0.f;
        for (int cc = 0; cc < DD; cc++) {
            float p = proj[mm*DD + cc];
            s1 += bp1s[b*DD+cc] * p; s2 += bp2s[b*DD+cc] * p;
        }
        d_bd1[b*MM+mm] = s1; d_bd2[b*MM+mm] = s2;
    }
    // per-batch constant part of layer-0 gate gemms (te,we quarters)
    for (int cc = c; cc < CC; cc += 32) {
        float si = 0.f, so = 0.f;
        for (int g = 0; g < DD; g++) {
            float tg = tesh[b*DD+g], wg = wesh[b*DD+g];
            si += tg * in_w [cc*CC + 64 + g] + wg * in_w [cc*CC + 96 + g];
            so += tg * out_w[cc*CC + 64 + g] + wg * out_w[cc*CC + 96 + g];
        }
        d_bgi[b*CC+cc] = si; d_bgo[b*CC+cc] = so;
    }
}

// -------------- per-node tables (+ colmax, + kv zero, + layer-0 node-gate) ------
__global__ __launch_bounds__(128) void k_node(
    const float* __restrict__ node_emb, const float* __restrict__ w1_w,
    const float* __restrict__ w2_w, const float* __restrict__ proj,
    const float* __restrict__ in_w, const float* __restrict__ out_w)
{
    __shared__ float w1s[DD*DD], w2s[DD*DD], ps[MM*DD];
    __shared__ float wgi[CC*DD], wgo[CC*DD];
    int tid = threadIdx.x;
    {
        int gid = blockIdx.x*128 + tid;
        for (int i = gid; i < (3*BB*MM*CC)/4; i += 20096)
            *(float4*)&d_kv[i*4] = make_float4(0.f,0.f,0.f,0.f);
    }
    for (int i = tid; i < DD*DD; i += 128) {
        int c = i >> 5, g = i & 31;
        w1s[i] = w1_w[c*(3*DD) + g];
        w2s[i] = w2_w[c*(3*DD) + g];
    }
    for (int i = tid; i < MM*DD; i += 128) ps[i] = proj[i];
    for (int i = tid; i < CC*DD; i += 128) {
        int c = i >> 5, g = i & 31;
        wgi[i] = in_w [c*CC + DD + g];
        wgo[i] = out_w[c*CC + DD + g];
    }
    __syncthreads();
    int n = blockIdx.x * 128 + tid;
    if (n >= NN) return;
    float e[DD];
#pragma unroll
    for (int q = 0; q < DD/4; q++) {
        float4 v = *(const float4*)&node_emb[n*DD + q*4];
        e[q*4+0]=v.x; e[q*4+1]=v.y; e[q*4+2]=v.z; e[q*4+3]=v.w;
    }
    float np1[DD], np2[DD];
#pragma unroll 4
    for (int c = 0; c < DD; c++) {
        float s1 = 0.f, s2 = 0.f;
#pragma unroll
        for (int g = 0; g < DD; g++) { s1 += e[g]*w1s[c*DD+g]; s2 += e[g]*w2s[c*DD+g]; }
        np1[c] = s1 * SC; np2[c] = s2 * SC;
        d_np1[n*DD+c] = np1[c]; d_np2[n*DD+c] = np2[c];
    }
#pragma unroll 2
    for (int m = 0; m < MM; m++) {
        float s1 = 0.f, s2 = 0.f;
#pragma unroll
        for (int c = 0; c < DD; c++) { float p = ps[m*DD+c]; s1 += np1[c]*p; s2 += np2[c]*p; }
        d_nd1[n*MM+m] = s1; d_nd2[n*MM+m] = s2;
        float mx = s2;
#pragma unroll
        for (int o = 16; o >= 1; o >>= 1)
            mx = fmaxf(mx, __shfl_xor_sync(0xffffffffu, mx, o));
        if ((tid & 31) == 0) atomicMax(&d_colenc[m], fenc(mx));
    }
#pragma unroll 2
    for (int c = 0; c < CC; c++) {
        float s1 = 0.f, s2 = 0.f;
#pragma unroll
        for (int g = 0; g < DD; g++) { s1 += e[g]*wgi[c*DD+g]; s2 += e[g]*wgo[c*DD+g]; }
        d_ngi[(size_t)n*CC + c] = s1;
        d_ngo[(size_t)n*CC + c] = s2;
    }
}

// ------------------------- embedding + phi + h0 + skip --------------------------
__global__ __launch_bounds__(256) void k_embed(
    const float* __restrict__ x, const float* __restrict__ node_emb,
    const float* __restrict__ input_w, const float* __restrict__ reg_w)
{
    __shared__ __align__(16) float wts[TT*DD];
    __shared__ float rw1s[PP*2*DD];
    __shared__ float bis[DD], bp1s[DD], bp2s[DD], tes[DD], wes[DD];
    __shared__ float bd1s[MM], bd2s[MM], cmax[MM];
    __shared__ float skb[PP];
    __shared__ float stab2s;

    int b = blockIdx.y; int tid = threadIdx.x;
    for (int i = tid; i < TT*DD; i += 256) {
        int t = i >> 5, c = i & 31;
        wts[i] = input_w[c*(3*TT) + t];
    }
    for (int i = tid; i < PP*2*DD; i += 256) {
        int p = i >> 6, k = i & 63;
        rw1s[i] = reg_w[p*(2*CC) + k];
    }
    if (tid < DD) {
        bis[tid]  = d_biasin[b*DD+tid];
        bp1s[tid] = d_bp1[b*DD+tid]; bp2s[tid] = d_bp2[b*DD+tid];
        tes[tid]  = d_te[b*DD+tid];  wes[tid]  = d_we[b*DD+tid];
    }
    if (tid < MM) {
        bd1s[tid] = d_bd1[b*MM+tid]; bd2s[tid] = d_bd2[b*MM+tid];
        cmax[tid] = fdec(d_colenc[tid]) + d_bd2[b*MM+tid];
    }
    if (tid < PP) skb[tid] = d_skipb[b*PP+tid];
    __syncthreads();
    if (tid == 0) {
        float mx = -1e30f;
        for (int i = 0; i < MM; i++) mx = fmaxf(mx, cmax[i]);
        stab2s = mx;
    }
    __syncthreads();

    int n = blockIdx.x*256 + tid;
    if (n >= NN) return;

    ull acc2[16];
#pragma unroll
    for (int q = 0; q < 16; q++) acc2[q] = 0ULL;
#pragma unroll 4
    for (int t = 0; t < TT; t++) {
        ull xp = dupf(x[b*(TT*NN) + t*NN + n]);
#pragma unroll
        for (int q = 0; q < 8; q++) {
            ulonglong2 w = *(const ulonglong2*)&wts[t*DD + q*4];
            ffma2(acc2[q*2+0], xp, w.x);
            ffma2(acc2[q*2+1], xp, w.y);
        }
    }
    float acc[DD];
#pragma unroll
    for (int q = 0; q < 16; q++) {
        float2 f = u2f(acc2[q]);
        acc[q*2+0] = f.x + bis[q*2+0];
        acc[q*2+1] = f.y + bis[q*2+1];
    }

    float ne[DD];
#pragma unroll
    for (int q = 0; q < DD/4; q++) {
        float4 v = *(const float4*)&node_emb[n*DD + q*4];
        ne[q*4+0]=v.x; ne[q*4+1]=v.y; ne[q*4+2]=v.z; ne[q*4+3]=v.w;
    }

    size_t hb = ((size_t)b*NN + n)*CC;
    size_t xb = ((size_t)b*NN + n)*DD;
#pragma unroll
    for (int q = 0; q < DD/4; q++) {
        float4 av = make_float4(acc[q*4], acc[q*4+1], acc[q*4+2], acc[q*4+3]);
        *(float4*)&d_h[hb + 0  + q*4] = av;
        *(float4*)&d_xin[xb + q*4] = av;
        *(float4*)&d_h[hb + 32 + q*4] = make_float4(ne[q*4],  ne[q*4+1],  ne[q*4+2],  ne[q*4+3]);
        *(float4*)&d_h[hb + 64 + q*4] = make_float4(tes[q*4], tes[q*4+1], tes[q*4+2], tes[q*4+3]);
        *(float4*)&d_h[hb + 96 + q*4] = make_float4(wes[q*4], wes[q*4+1], wes[q*4+2], wes[q*4+3]);
    }

    size_t sb = ((size_t)b*NN + n)*PP;
#pragma unroll
    for (int p = 0; p < PP; p++) {
        float s = skb[p];
#pragma unroll
        for (int c = 0; c < DD; c++)
            s += acc[c]*rw1s[p*64 + c] + ne[c]*rw1s[p*64 + 32 + c];
        d_skip[sb + p] = s;
    }

    // ---- phi_q ----
    {
        float np[DD];
#pragma unroll
        for (int q = 0; q < DD/4; q++) {
            float4 v = *(const float4*)&d_np1[n*DD + q*4];
            np[q*4]=v.x; np[q*4+1]=v.y; np[q*4+2]=v.z; np[q*4+3]=v.w;
        }
        float dg = 0.f;
#pragma unroll
        for (int c = 0; c < DD; c++) { float t = np[c]+bp1s[c]; dg += t*t; }
        dg *= 0.5f;
        float mx = -1e30f;
#pragma unroll 4
        for (int m = 0; m < MM; m++) mx = fmaxf(mx, d_nd1[n*MM+m] + bd1s[m]);
        float sub = dg + mx;
        size_t pb = ((size_t)b*NN + n)*MM;
#pragma unroll
        for (int q = 0; q < MM/4; q++) {
            float4 v = *(const float4*)&d_nd1[n*MM + q*4];
            float4 o;
            o.x = RATIO*(__expf(v.x + bd1s[q*4+0] - sub) + EPSF);
            o.y = RATIO*(__expf(v.y + bd1s[q*4+1] - sub) + EPSF);
            o.z = RATIO*(__expf(v.z + bd1s[q*4+2] - sub) + EPSF);
            o.w = RATIO*(__expf(v.w + bd1s[q*4+3] - sub) + EPSF);
            *(float4*)&d_phiq[pb + q*4] = o;
        }
    }
    // ---- phi_k ----
    {
        float np[DD];
#pragma unroll
        for (int q = 0; q < DD/4; q++) {
            float4 v = *(const float4*)&d_np2[n*DD + q*4];
            np[q*4]=v.x; np[q*4+1]=v.y; np[q*4+2]=v.z; np[q*4+3]=v.w;
        }
        float dg = 0.f;
#pragma unroll
        for (int c = 0; c < DD; c++) { float t = np[c]+bp2s[c]; dg += t*t; }
        dg *= 0.5f;
        float sub = dg + stab2s;
        size_t pb = ((size_t)b*NN + n)*MM;
#pragma unroll
        for (int q = 0; q < MM/4; q++) {
            float4 v = *(const float4*)&d_nd2[n*MM + q*4];
            float4 o;
            o.x = RATIO*(__expf(v.x + bd2s[q*4+0] - sub) + EPSF);
            o.y = RATIO*(__expf(v.y + bd2s[q*4+1] - sub) + EPSF);
            o.z = RATIO*(__expf(v.z + bd2s[q*4+2] - sub) + EPSF);
            o.w = RATIO*(__expf(v.w + bd2s[q*4+3] - sub) + EPSF);
            *(float4*)&d_phik[pb + q*4] = o;
        }
    }
}

// ------------------------- ksum (layer-invariant) -------------------------------
__global__ __launch_bounds__(256) void k_ksum()
{
    int tid = threadIdx.x, b = blockIdx.y;
    int m = tid & 63, sub = tid >> 6;
    float partial = 0.f;
    for (int i = 0; i < 64; i++) {
        int n = blockIdx.x*256 + sub + i*4;
        if (n < NN) partial += d_phik[((size_t)b*NN + n)*MM + m];
    }
    __shared__ float red[256];
    red[tid] = partial; __syncthreads();
    if (tid < 64)
        atomicAdd(&d_ksum[b*MM + tid], red[tid] + red[tid+64] + red[tid+128] + red[tid+192]);
}

// -------- layer-0 fused gate + kv: K=32 gemm + node/batch table adds -------------
#define G0_SMEM 147456
__global__ __launch_bounds__(512) void k_gate0(
    const float* __restrict__ in_w, const float* __restrict__ in_b,
    const float* __restrict__ out_w, const float* __restrict__ out_b)
{
    extern __shared__ float sm0[];
    float* wi_s = sm0;              // [32k][128c]
    float* wo_s = sm0 + 4096;
    float* xs   = sm0 + 8192;       // [128n][32k]
    float* phis = sm0 + 12288;      // [128n][64m]
    float* us   = sm0 + 20480;      // [128n][128c]
    __shared__ float ibs[CC], obs[CC], bgis[CC], bgos[CC];

    int tid = threadIdx.x, b = blockIdx.y;
    for (int j = tid; j < 1024; j += 512) {
        int c = j & 127, kq = j >> 7;
        float4 vi = *(const float4*)&in_w [c*CC + kq*4];
        float4 vo = *(const float4*)&out_w[c*CC + kq*4];
        wi_s[(kq*4+0)*CC + c] = vi.x; wi_s[(kq*4+1)*CC + c] = vi.y;
        wi_s[(kq*4+2)*CC + c] = vi.z; wi_s[(kq*4+3)*CC + c] = vi.w;
        wo_s[(kq*4+0)*CC + c] = vo.x; wo_s[(kq*4+1)*CC + c] = vo.y;
        wo_s[(kq*4+2)*CC + c] = vo.z; wo_s[(kq*4+3)*CC + c] = vo.w;
    }
    if (tid < CC) {
        ibs[tid] = in_b[tid];  obs[tid] = out_b[tid];
        bgis[tid] = d_bgi[b*CC+tid]; bgos[tid] = d_bgo[b*CC+tid];
    }

    int cg = tid & 31, ng = tid >> 5;
    int c4 = cg*4;
    int km8 = (ng & 7) * 8;
    int kc2 = ((ng >> 3) ? 64 : 0) + cg*2;
    ull kvacc[4][2];
#pragma unroll
    for (int mp = 0; mp < 4; mp++) { kvacc[mp][0] = 0ULL; kvacc[mp][1] = 0ULL; }

    const int NT = (NN + 127) / 128;
    for (int tile = blockIdx.x; tile < NT; tile += GX) {
        int n0 = tile*128;
        __syncthreads();
        for (int i = tid; i < 1024; i += 512) {
            int r = i >> 3, kq = (i & 7)*4;
            int n = n0 + r;
            float4 v = (n < NN) ? *(const float4*)&d_xin[((size_t)b*NN + n)*DD + kq]
                                : make_float4(0.f,0.f,0.f,0.f);
            *(float4*)&xs[r*DD + kq] = v;
        }
        for (int i = tid; i < 2048; i += 512) {
            int r = i >> 4, mq = (i & 15)*4;
            int n = n0 + r;
            float4 v = (n < NN) ? *(const float4*)&d_phik[((size_t)b*NN + n)*MM + mq]
                                : make_float4(0.f,0.f,0.f,0.f);
            *(float4*)&phis[r*MM + mq] = v;
        }
        __syncthreads();

        ull ai[8][2], ao[8][2];
#pragma unroll
        for (int j = 0; j < 8; j++) { ai[j][0]=0ULL; ai[j][1]=0ULL; ao[j][0]=0ULL; ao[j][1]=0ULL; }

#pragma unroll 4
        for (int k = 0; k < DD; k++) {
            ulonglong2 wi = *(const ulonglong2*)&wi_s[k*CC + c4];
            ulonglong2 wo = *(const ulonglong2*)&wo_s[k*CC + c4];
#pragma unroll
            for (int j = 0; j < 8; j++) {
                ull hp = dupf(xs[(ng*8+j)*DD + k]);
                ffma2(ai[j][0], hp, wi.x); ffma2(ai[j][1], hp, wi.y);
                ffma2(ao[j][0], hp, wo.x); ffma2(ao[j][1], hp, wo.y);
            }
        }

#pragma unroll
        for (int j = 0; j < 8; j++) {
            int r = ng*8 + j;
            int n = n0 + r;
            float4 u;
            if (n < NN) {
                float4 gi = *(const float4*)&d_ngi[(size_t)n*CC + c4];
                float4 go = *(const float4*)&d_ngo[(size_t)n*CC + c4];
                float2 a0 = u2f(ai[j][0]), a1 = u2f(ai[j][1]);
                float2 o0 = u2f(ao[j][0]), o1 = u2f(ao[j][1]);
                float i0 = a0.x + gi.x + bgis[c4+0] + ibs[c4+0];
                float i1 = a0.y + gi.y + bgis[c4+1] + ibs[c4+1];
                float i2 = a1.x + gi.z + bgis[c4+2] + ibs[c4+2];
                float i3 = a1.y + gi.w + bgis[c4+3] + ibs[c4+3];
                float v0 = o0.x + go.x + bgos[c4+0] + obs[c4+0];
                float v1 = o0.y + go.y + bgos[c4+1] + obs[c4+1];
                float v2 = o1.x + go.z + bgos[c4+2] + obs[c4+2];
                float v3 = o1.y + go.w + bgos[c4+3] + obs[c4+3];
                u.x = v0 / (1.f + __expf(-i0));
                u.y = v1 / (1.f + __expf(-i1));
                u.z = v2 / (1.f + __expf(-i2));
                u.w = v3 / (1.f + __expf(-i3));
            } else {
                u = make_float4(0.f, 0.f, 0.f, 0.f);
            }
            *(float4*)&us[r*CC + c4] = u;
        }
        __syncthreads();

#pragma unroll 2
        for (int n = 0; n < 128; n++) {
            ull u0 = dupf(us[n*CC + kc2 + 0]);
            ull u1 = dupf(us[n*CC + kc2 + 1]);
#pragma unroll
            for (int mp = 0; mp < 4; mp++) {
                ull phv = *(const ull*)&phis[n*MM + km8 + 2*mp];
                ffma2(kvacc[mp][0], phv, u0);
                ffma2(kvacc[mp][1], phv, u1);
            }
        }
    }

    float* kvb = &d_kv[(size_t)b*(MM*CC)];    // layer 0
#pragma unroll
    for (int mp = 0; mp < 4; mp++) {
        float2 f0 = u2f(kvacc[mp][0]);
        float2 f1 = u2f(kvacc[mp][1]);
        int m0 = km8 + 2*mp;
        atomicAdd(&kvb[(m0+0)*CC + kc2 + 0], f0.x);
        atomicAdd(&kvb[(m0+1)*CC + kc2 + 0], f0.y);
        atomicAdd(&kvb[(m0+0)*CC + kc2 + 1], f1.x);
        atomicAdd(&kvb[(m0+1)*CC + kc2 + 1], f1.y);
    }
}

// ---- fused gate + kv (layers 1,2): channel-half split, 2 CTAs/SM ----------------
// CTA: 64-node tile x 64-channel half. grid (38, BB) = 304 CTAs = 2/SM.
// smem (floats): wi[128k][64c] @0, wo @8192, hs[64n][132] @16384 (u[64n][64c]
// reuses hs region), phis[64n][64m] @24832. Total 28928 f = 115712 B.
#define GK_SMEM 115712
__global__ __launch_bounds__(256) void k_gatekv(int layer,
    const float* __restrict__ in_w, const float* __restrict__ in_b,
    const float* __restrict__ out_w, const float* __restrict__ out_b)
{
    extern __shared__ float sm[];
    float* wi_s = sm;
    float* wo_s = sm + 8192;
    float* hs   = sm + 16384;      // stride 132
    float* us   = sm + 16384;      // stride 64 (reuse)
    float* phis = sm + 24832;
    __shared__ float ibs[64], obs[64];

    int tid = threadIdx.x, b = blockIdx.y;
    int half = blockIdx.x & 1, tg = blockIdx.x >> 1;
    const float* wil = in_w  + layer*CC*CC + half*64*CC;
    const float* wol = out_w + layer*CC*CC + half*64*CC;
    // weights: 64 channel rows x 128 k -> [k][c] smem (one-time)
    for (int j = tid; j < 2048; j += 256) {
        int c = j & 63, kq = j >> 6;             // kq 0..31
        float4 vi = *(const float4*)&wil[c*CC + kq*4];
        float4 vo = *(const float4*)&wol[c*CC + kq*4];
        wi_s[(kq*4+0)*64 + c] = vi.x; wi_s[(kq*4+1)*64 + c] = vi.y;
        wi_s[(kq*4+2)*64 + c] = vi.z; wi_s[(kq*4+3)*64 + c] = vi.w;
        wo_s[(kq*4+0)*64 + c] = vo.x; wo_s[(kq*4+1)*64 + c] = vo.y;
        wo_s[(kq*4+2)*64 + c] = vo.z; wo_s[(kq*4+3)*64 + c] = vo.w;
    }
    if (tid < 64) {
        ibs[tid] = in_b[layer*CC + half*64 + tid];
        obs[tid] = out_b[layer*CC + half*64 + tid];
    }

    int lane = tid & 31, w = tid >> 5;           // 8 warps
    int nhalf = lane >> 4, cl = lane & 15;
    int cq = cl*4;
    int rbase = w*8 + nhalf*4;                   // 4 nodes per lane
    int m8 = w*8;                                // kv: warp -> m-octet
    int kc2 = lane*2;                            // kv: 2 channels (local)
    ull kvacc[4][2];
#pragma unroll
    for (int mp = 0; mp < 4; mp++) { kvacc[mp][0] = 0ULL; kvacc[mp][1] = 0ULL; }

    const int NT = (NN + 63) / 64;               // 313
    for (int tile = tg; tile < NT; tile += 19) {
        int n0 = tile*64;
        __syncthreads();                         // prev kv done with us/phis
        for (int j = tid; j < 2048; j += 256) {
            int r = j >> 5, kq = j & 31;
            int n = n0 + r;
            float4 v = (n < NN) ? *(const float4*)&d_h[((size_t)b*NN + n)*CC + kq*4]
                                : make_float4(0.f,0.f,0.f,0.f);
            *(float4*)&hs[r*132 + kq*4] = v;
        }
        for (int j = tid; j < 1024; j += 256) {
            int r = j >> 4, mq = (j & 15)*4;
            int n = n0 + r;
            float4 v = (n < NN) ? *(const float4*)&d_phik[((size_t)b*NN + n)*MM + mq]
                                : make_float4(0.f,0.f,0.f,0.f);
            *(float4*)&phis[r*64 + mq] = v;
        }
        __syncthreads();

        ull ai[4][2], ao[4][2];
#pragma unroll
        for (int j = 0; j < 4; j++) { ai[j][0]=0ULL; ai[j][1]=0ULL; ao[j][0]=0ULL; ao[j][1]=0ULL; }

#pragma unroll 2
        for (int k = 0; k < CC; k++) {
            ulonglong2 wi = *(const ulonglong2*)&wi_s[k*64 + cq];
            ulonglong2 wo = *(const ulonglong2*)&wo_s[k*64 + cq];
#pragma unroll
            for (int j = 0; j < 4; j++) {
                ull hp = dupf(hs[(rbase+j)*132 + k]);
                ffma2(ai[j][0], hp, wi.x); ffma2(ai[j][1], hp, wi.y);
                ffma2(ao[j][0], hp, wo.x); ffma2(ao[j][1], hp, wo.y);
            }
        }
        __syncthreads();                         // all gemm reads of hs done

#pragma unroll
        for (int j = 0; j < 4; j++) {
            int r = rbase + j;
            int n = n0 + r;
            float4 u;
            if (n < NN) {
                float2 a0 = u2f(ai[j][0]), a1 = u2f(ai[j][1]);
                float2 o0 = u2f(ao[j][0]), o1 = u2f(ao[j][1]);
                u.x = (o0.x + obs[cq+0]) / (1.f + __expf(-(a0.x + ibs[cq+0])));
                u.y = (o0.y + obs[cq+1]) / (1.f + __expf(-(a0.y + ibs[cq+1])));
                u.z = (o1.x + obs[cq+2]) / (1.f + __expf(-(a1.x + ibs[cq+2])));
                u.w = (o1.y + obs[cq+3]) / (1.f + __expf(-(a1.y + ibs[cq+3])));
            } else {
                u = make_float4(0.f, 0.f, 0.f, 0.f);
            }
            *(float4*)&us[r*64 + cq] = u;
        }
        __syncthreads();                         // u tile visible

#pragma unroll 2
        for (int n = 0; n < 64; n++) {
            ull u0 = dupf(us[n*64 + kc2 + 0]);
            ull u1 = dupf(us[n*64 + kc2 + 1]);
#pragma unroll
            for (int mp = 0; mp < 4; mp++) {
                ull phv = *(const ull*)&phis[n*64 + m8 + 2*mp];
                ffma2(kvacc[mp][0], phv, u0);
                ffma2(kvacc[mp][1], phv, u1);
            }
        }
    }

    float* kvb = &d_kv[((size_t)layer*BB + b)*(MM*CC)] + half*64;
#pragma unroll
    for (int mp = 0; mp < 4; mp++) {
        float2 f0 = u2f(kvacc[mp][0]);
        float2 f1 = u2f(kvacc[mp][1]);
        int m0 = m8 + 2*mp;
        atomicAdd(&kvb[(m0+0)*CC + kc2 + 0], f0.x);
        atomicAdd(&kvb[(m0+1)*CC + kc2 + 0], f0.y);
        atomicAdd(&kvb[(m0+0)*CC + kc2 + 1], f1.x);
        atomicAdd(&kvb[(m0+1)*CC + kc2 + 1], f1.y);
    }
}

// ------------------------- num/den + residual + LN (f32x2) -----------------------
__global__ __launch_bounds__(256) void k_numln(int layer,
    const float* __restrict__ ln_g, const float* __restrict__ ln_b)
{
    extern __shared__ float kvs[];               // 32 KB dynamic (opted-in)
    __shared__ ull phis2[32*MM];
    __shared__ ull ksd[MM];
    __shared__ float lg[CC], lb[CC];
    int tid = threadIdx.x, b = blockIdx.y, chunk = blockIdx.x;
    for (int i = tid*4; i < MM*CC; i += 1024)
        *(float4*)&kvs[i] = *(const float4*)&d_kv[((size_t)layer*BB + b)*(MM*CC) + i];
    if (tid < MM) ksd[tid] = dupf(d_ksum[b*MM+tid]);
    if (tid < CC) { lg[tid] = ln_g[layer*CC+tid]; lb[tid] = ln_b[layer*CC+tid]; }
    __syncthreads();

    int cg = tid & 31, ng = tid >> 5;
    int c4 = cg*4;

    for (int t = 0; t < 16; t++) {
        int n0 = chunk*512 + t*32;
        if (n0 >= NN) break;
        __syncthreads();
        for (int i = tid; i < 512; i += 256) {
            int r = i >> 4, mq = (i & 15)*4;
            int n = n0 + r;
            float4 v = (n < NN) ? *(const float4*)&d_phiq[((size_t)b*NN+n)*MM + mq]
                                : make_float4(0.f,0.f,0.f,0.f);
            phis2[r*MM+mq+0] = dupf(v.x);
            phis2[r*MM+mq+1] = dupf(v.y);
            phis2[r*MM+mq+2] = dupf(v.z);
            phis2[r*MM+mq+3] = dupf(v.w);
        }
        __syncthreads();

        ull an[4][2], ad2[4];
#pragma unroll
        for (int j = 0; j < 4; j++) { an[j][0]=0ULL; an[j][1]=0ULL; ad2[j]=0ULL; }
#pragma unroll 2
        for (int m = 0; m < MM; m++) {
            ulonglong2 kf = *(const ulonglong2*)&kvs[m*CC + c4];
            ull ks = ksd[m];
#pragma unroll
            for (int j = 0; j < 4; j++) {
                ull pq = phis2[(ng*4+j)*MM + m];
                ffma2(an[j][0], pq, kf.x);
                ffma2(an[j][1], pq, kf.y);
                ffma2(ad2[j],   pq, ks);
            }
        }
#pragma unroll
        for (int j = 0; j < 4; j++) {
            int n = n0 + ng*4 + j;
            if (n >= NN) continue;   // warp-uniform
            size_t base = ((size_t)b*NN + n)*CC + c4;
            float4 hv = *(const float4*)&d_h[base];
            float2 n0f = u2f(an[j][0]), n1f = u2f(an[j][1]);
            float inv = 1.f / u2f(ad2[j]).x;
            float v0 = n0f.x*inv + hv.x;
            float v1 = n0f.y*inv + hv.y;
            float v2 = n1f.x*inv + hv.z;
            float v3 = n1f.y*inv + hv.w;
            float s1 = v0+v1+v2+v3;
            float s2 = v0*v0+v1*v1+v2*v2+v3*v3;
#pragma unroll
            for (int o = 16; o >= 1; o >>= 1) {
                s1 += __shfl_xor_sync(0xffffffffu, s1, o);
                s2 += __shfl_xor_sync(0xffffffffu, s2, o);
            }
            float mu = s1*(1.f/128.f);
            float var = s2*(1.f/128.f) - mu*mu;
            float rs = rsqrtf(var + 1e-5f);
            float4 o4;
            o4.x = (v0-mu)*rs*lg[c4+0] + lb[c4+0];
            o4.y = (v1-mu)*rs*lg[c4+1] + lb[c4+1];
            o4.z = (v2-mu)*rs*lg[c4+2] + lb[c4+2];
            o4.w = (v3-mu)*rs*lg[c4+3] + lb[c4+3];
            *(float4*)&d_h[base] = o4;
        }
    }
}

// ------------------------- final regression --------------------------------------
__global__ __launch_bounds__(256) void k_out(
    const float* __restrict__ reg_w, const float* __restrict__ reg_b,
    float* __restrict__ out)
{
    __shared__ float rw2s[PP*CC];
    __shared__ float rbs[PP];
    int tid = threadIdx.x, b = blockIdx.y;
    for (int i = tid; i < PP*CC; i += 256) {
        int p = i >> 7, c = i & 127;
        rw2s[i] = reg_w[p*(2*CC) + CC + c];
    }
    if (tid < PP) rbs[tid] = reg_b[tid];
    __syncthreads();
    int n = blockIdx.x*256 + tid;
    if (n >= NN) return;
    float a[PP];
    size_t sb = ((size_t)b*NN + n)*PP;
#pragma unroll
    for (int p = 0; p < PP; p++) a[p] = d_skip[sb + p] + rbs[p];
    size_t hb = ((size_t)b*NN + n)*CC;
#pragma unroll 4
    for (int q = 0; q < CC/4; q++) {
        float4 hv = *(const float4*)&d_h[hb + q*4];
#pragma unroll
        for (int p = 0; p < PP; p++) {
            a[p] += hv.x*rw2s[p*CC + q*4+0] + hv.y*rw2s[p*CC + q*4+1]
                  + hv.z*rw2s[p*CC + q*4+2] + hv.w*rw2s[p*CC + q*4+3];
        }
    }
#pragma unroll
    for (int p = 0; p < PP; p++)
        out[(b*PP + p)*NN + n] = a[p];
}

// ------------------------- launch ------------------------------------------------
extern "C" void kernel_launch(void* const* d_in, const int* in_sizes, int n_in,
                              void* d_out, int out_size)
{
    const float* x        = (const float*)d_in[0];
    const float* x_mark   = (const float*)d_in[1];
    const float* node_emb = (const float*)d_in[2];
    const float* time_tab = (const float*)d_in[3];
    const float* week_tab = (const float*)d_in[4];
    const float* input_w  = (const float*)d_in[5];
    const float* input_b  = (const float*)d_in[6];
    const float* w1_w     = (const float*)d_in[7];
    const float* w1_b     = (const float*)d_in[8];
    const float* w2_w     = (const float*)d_in[9];
    const float* w2_b     = (const float*)d_in[10];
    const float* in_w     = (const float*)d_in[11];
    const float* in_b     = (const float*)d_in[12];
    const float* out_w    = (const float*)d_in[13];
    const float* out_b    = (const float*)d_in[14];
    const float* ln_g     = (const float*)d_in[15];
    const float* ln_b     = (const float*)d_in[16];
    const float* reg_w    = (const float*)d_in[17];
    const float* reg_b    = (const float*)d_in[18];
    const float* proj     = (const float*)d_in[19];
    float* out = (float*)d_out;

    cudaFuncSetAttribute(k_gate0,  cudaFuncAttributeMaxDynamicSharedMemorySize, G0_SMEM);
    cudaFuncSetAttribute(k_gatekv, cudaFuncAttributeMaxDynamicSharedMemorySize, GK_SMEM);
    cudaFuncSetAttribute(k_numln,  cudaFuncAttributeMaxDynamicSharedMemorySize, 32768);

    k_batch<<<1, 256>>>(x_mark, time_tab, week_tab, w1_w, w1_b, w2_w, w2_b,
                        input_w, input_b, proj, reg_w, in_w, out_w);
    k_node<<<(NN+127)/128, 128>>>(node_emb, w1_w, w2_w, proj, in_w, out_w);
    k_embed<<<dim3((NN+255)/256, BB), 256>>>(x, node_emb, input_w, reg_w);
    // layer-0 fused gate+kv is the 4th launch -> profiled by ncu
    k_gate0<<<dim3(GX, BB), 512, G0_SMEM>>>(in_w, in_b, out_w, out_b);
    k_ksum<<<dim3((NN+255)/256, BB), 256>>>();
    k_numln<<<dim3(40, BB), 256, 32768>>>(0, ln_g, ln_b);
    for (int l = 1; l < 3; l++) {
        k_gatekv<<<dim3(38, BB), 256, GK_SMEM>>>(l, in_w, in_b, out_w, out_b);
        k_numln<<<dim3(40, BB), 256, 32768>>>(l, ln_g, ln_b);
    }
    k_out<<<dim3((NN+255)/256, BB), 256>>>(reg_w, reg_b, out);
}

// round 15
// speedup vs baseline: 1.0556x; 1.0556x over previous
#include <cuda_runtime.h>
#include <math.h>
#include <stdint.h>

#define BB 8
#define TT 96
#define NN 20000
#define PP 12
#define DD 32
#define CC 128
#define MM 64
#define GX 18   // gate grid.x (144 CTAs, 1/SM)
// 2 * 32^-0.25  (inv_sqrt_tau * d^-1/4)
#define SC 0.8408964152537145f
#define RATIO 0.125f
#define EPSF 1e-6f

typedef unsigned long long ull;

// ---- packed f32x2 helpers ----------------------------------------------------
__device__ __forceinline__ void ffma2(ull& d, ull a, ull b) {
    asm("fma.rn.f32x2 %0, %1, %2, %0;" : "+l"(d) : "l"(a), "l"(b));
}
__device__ __forceinline__ ull dupf(float v) {
    ull r; asm("mov.b64 %0, {%1, %1};" : "=l"(r) : "f"(v)); return r;
}
__device__ __forceinline__ float2 u2f(ull v) {
    float2 f; asm("mov.b64 {%0, %1}, %2;" : "=f"(f.x), "=f"(f.y) : "l"(v)); return f;
}

// ---- ordered-uint encoding for float atomicMax --------------------------------
__device__ __forceinline__ unsigned fenc(float f) {
    unsigned b = __float_as_uint(f);
    return (b & 0x80000000u) ? ~b : (b | 0x80000000u);
}
__device__ __forceinline__ float fdec(unsigned e) {
    unsigned b = (e & 0x80000000u) ? (e ^ 0x80000000u) : ~e;
    return __uint_as_float(b);
}

// ------------------------- static device scratch -----------------------------
__device__ float d_h[BB*NN*CC];
__device__ float d_xin[BB*NN*DD];
__device__ float d_ngi[NN*CC];
__device__ float d_ngo[NN*CC];
__device__ float d_bgi[BB*CC];
__device__ float d_bgo[BB*CC];
__device__ float d_phiq[BB*NN*MM];
__device__ float d_phik[BB*NN*MM];
__device__ float d_skip[BB*NN*PP];
__device__ float d_np1[NN*DD], d_np2[NN*DD];
__device__ float d_nd1[NN*MM], d_nd2[NN*MM];
__device__ unsigned d_colenc[MM];
__device__ float d_bp1[BB*DD], d_bp2[BB*DD];
__device__ float d_bd1[BB*MM], d_bd2[BB*MM];
__device__ float d_biasin[BB*DD];
__device__ float d_te[BB*DD], d_we[BB*DD];
__device__ float d_skipb[BB*PP];
__device__ float d_kv[3*BB*MM*CC];
__device__ float d_ksum[BB*MM];

// ------------------------- per-batch constants --------------------------------
__global__ __launch_bounds__(256) void k_batch(
    const float* __restrict__ x_mark, const float* __restrict__ time_tab,
    const float* __restrict__ week_tab,
    const float* __restrict__ w1_w, const float* __restrict__ w1_b,
    const float* __restrict__ w2_w, const float* __restrict__ w2_b,
    const float* __restrict__ input_w, const float* __restrict__ input_b,
    const float* __restrict__ proj, const float* __restrict__ reg_w,
    const float* __restrict__ in_w, const float* __restrict__ out_w)
{
    __shared__ float bp1s[BB*DD], bp2s[BB*DD];
    __shared__ float tesh[BB*DD], wesh[BB*DD];
    __shared__ int tods[BB], dows[BB];
    int tid = threadIdx.x;
    if (tid < MM) d_colenc[tid] = 0u;
    d_ksum[tid] = 0.f;
    d_ksum[256 + tid] = 0.f;
    if (tid < BB) {
        float v0 = x_mark[tid*TT*2 + (TT-1)*2 + 0];
        float v1 = x_mark[tid*TT*2 + (TT-1)*2 + 1];
        int ti = (int)(v0 * (float)TT); ti = ti < 0 ? 0 : (ti > TT-1 ? TT-1 : ti);
        int di = (int)(v1 * 7.0f);      di = di < 0 ? 0 : (di > 6 ? 6 : di);
        tods[tid] = ti; dows[tid] = di;
    }
    __syncthreads();
    int b = tid >> 5, c = tid & 31;
    float te = time_tab[tods[b]*DD + c];
    float we = week_tab[dows[b]*DD + c];
    d_te[b*DD+c] = te; d_we[b*DD+c] = we;
    tesh[b*DD+c] = te; wesh[b*DD+c] = we;

    float a1 = w1_b[c], a2 = w2_b[c];
    for (int g = 0; g < DD; g++) {
        float tg = time_tab[tods[b]*DD+g], wg = week_tab[dows[b]*DD+g];
        a1 += tg * w1_w[c*(3*DD) + DD + g] + wg * w1_w[c*(3*DD) + 2*DD + g];
        a2 += tg * w2_w[c*(3*DD) + DD + g] + wg * w2_w[c*(3*DD) + 2*DD + g];
    }
    a1 *= SC; a2 *= SC;
    d_bp1[b*DD+c] = a1; d_bp2[b*DD+c] = a2;
    bp1s[b*DD+c] = a1;  bp2s[b*DD+c] = a2;

    float bi = input_b[c];
    for (int t = 0; t < TT; t++) {
        bi += x_mark[b*TT*2 + t*2 + 0] * input_w[c*(3*TT) + TT + t]
            + x_mark[b*TT*2 + t*2 + 1] * input_w[c*(3*TT) + 2*TT + t];
    }
    d_biasin[b*DD+c] = bi;

    if (c < PP) {
        float s = 0.f;
        for (int g = 0; g < DD; g++)
            s += time_tab[tods[b]*DD+g] * reg_w[c*(2*CC) + 2*DD + g]
               + week_tab[dows[b]*DD+g] * reg_w[c*(2*CC) + 3*DD + g];
        d_skipb[b*PP + c] = s;
    }
    __syncthreads();
    for (int mm = c; mm < MM; mm += 32) {
        float s1 = 0.f, s2 = 0.f;
        for (int cc = 0; cc < DD; cc++) {
            float p = proj[mm*DD + cc];
            s1 += bp1s[b*DD+cc] * p; s2 += bp2s[b*DD+cc] * p;
        }
        d_bd1[b*MM+mm] = s1; d_bd2[b*MM+mm] = s2;
    }
    // per-batch constant part of layer-0 gate gemms (te,we quarters)
    for (int cc = c; cc < CC; cc += 32) {
        float si = 0.f, so = 0.f;
        for (int g = 0; g < DD; g++) {
            float tg = tesh[b*DD+g], wg = wesh[b*DD+g];
            si += tg * in_w [cc*CC + 64 + g] + wg * in_w [cc*CC + 96 + g];
            so += tg * out_w[cc*CC + 64 + g] + wg * out_w[cc*CC + 96 + g];
        }
        d_bgi[b*CC+cc] = si; d_bgo[b*CC+cc] = so;
    }
}

// -------------- per-node tables (+ colmax, + kv zero, + layer-0 node-gate) ------
__global__ __launch_bounds__(128) void k_node(
    const float* __restrict__ node_emb, const float* __restrict__ w1_w,
    const float* __restrict__ w2_w, const float* __restrict__ proj,
    const float* __restrict__ in_w, const float* __restrict__ out_w)
{
    __shared__ float w1s[DD*DD], w2s[DD*DD], ps[MM*DD];
    __shared__ float wgi[CC*DD], wgo[CC*DD];
    int tid = threadIdx.x;
    {
        int gid = blockIdx.x*128 + tid;
        for (int i = gid; i < (3*BB*MM*CC)/4; i += 20096)
            *(float4*)&d_kv[i*4] = make_float4(0.f,0.f,0.f,0.f);
    }
    for (int i = tid; i < DD*DD; i += 128) {
        int c = i >> 5, g = i & 31;
        w1s[i] = w1_w[c*(3*DD) + g];
        w2s[i] = w2_w[c*(3*DD) + g];
    }
    for (int i = tid; i < MM*DD; i += 128) ps[i] = proj[i];
    for (int i = tid; i < CC*DD; i += 128) {
        int c = i >> 5, g = i & 31;
        wgi[i] = in_w [c*CC + DD + g];
        wgo[i] = out_w[c*CC + DD + g];
    }
    __syncthreads();
    int n = blockIdx.x * 128 + tid;
    if (n >= NN) return;
    float e[DD];
#pragma unroll
    for (int q = 0; q < DD/4; q++) {
        float4 v = *(const float4*)&node_emb[n*DD + q*4];
        e[q*4+0]=v.x; e[q*4+1]=v.y; e[q*4+2]=v.z; e[q*4+3]=v.w;
    }
    float np1[DD], np2[DD];
#pragma unroll 4
    for (int c = 0; c < DD; c++) {
        float s1 = 0.f, s2 = 0.f;
#pragma unroll
        for (int g = 0; g < DD; g++) { s1 += e[g]*w1s[c*DD+g]; s2 += e[g]*w2s[c*DD+g]; }
        np1[c] = s1 * SC; np2[c] = s2 * SC;
        d_np1[n*DD+c] = np1[c]; d_np2[n*DD+c] = np2[c];
    }
#pragma unroll 2
    for (int m = 0; m < MM; m++) {
        float s1 = 0.f, s2 = 0.f;
#pragma unroll
        for (int c = 0; c < DD; c++) { float p = ps[m*DD+c]; s1 += np1[c]*p; s2 += np2[c]*p; }
        d_nd1[n*MM+m] = s1; d_nd2[n*MM+m] = s2;
        float mx = s2;
#pragma unroll
        for (int o = 16; o >= 1; o >>= 1)
            mx = fmaxf(mx, __shfl_xor_sync(0xffffffffu, mx, o));
        if ((tid & 31) == 0) atomicMax(&d_colenc[m], fenc(mx));
    }
#pragma unroll 2
    for (int c = 0; c < CC; c++) {
        float s1 = 0.f, s2 = 0.f;
#pragma unroll
        for (int g = 0; g < DD; g++) { s1 += e[g]*wgi[c*DD+g]; s2 += e[g]*wgo[c*DD+g]; }
        d_ngi[(size_t)n*CC + c] = s1;
        d_ngo[(size_t)n*CC + c] = s2;
    }
}

// ------------------------- embedding + phi + h0 + skip --------------------------
__global__ __launch_bounds__(256) void k_embed(
    const float* __restrict__ x, const float* __restrict__ node_emb,
    const float* __restrict__ input_w, const float* __restrict__ reg_w)
{
    __shared__ __align__(16) float wts[TT*DD];
    __shared__ float rw1s[PP*2*DD];
    __shared__ float bis[DD], bp1s[DD], bp2s[DD], tes[DD], wes[DD];
    __shared__ float bd1s[MM], bd2s[MM], cmax[MM];
    __shared__ float skb[PP];
    __shared__ float stab2s;

    int b = blockIdx.y; int tid = threadIdx.x;
    for (int i = tid; i < TT*DD; i += 256) {
        int t = i >> 5, c = i & 31;
        wts[i] = input_w[c*(3*TT) + t];
    }
    for (int i = tid; i < PP*2*DD; i += 256) {
        int p = i >> 6, k = i & 63;
        rw1s[i] = reg_w[p*(2*CC) + k];
    }
    if (tid < DD) {
        bis[tid]  = d_biasin[b*DD+tid];
        bp1s[tid] = d_bp1[b*DD+tid]; bp2s[tid] = d_bp2[b*DD+tid];
        tes[tid]  = d_te[b*DD+tid];  wes[tid]  = d_we[b*DD+tid];
    }
    if (tid < MM) {
        bd1s[tid] = d_bd1[b*MM+tid]; bd2s[tid] = d_bd2[b*MM+tid];
        cmax[tid] = fdec(d_colenc[tid]) + d_bd2[b*MM+tid];
    }
    if (tid < PP) skb[tid] = d_skipb[b*PP+tid];
    __syncthreads();
    if (tid == 0) {
        float mx = -1e30f;
        for (int i = 0; i < MM; i++) mx = fmaxf(mx, cmax[i]);
        stab2s = mx;
    }
    __syncthreads();

    int n = blockIdx.x*256 + tid;
    if (n >= NN) return;

    ull acc2[16];
#pragma unroll
    for (int q = 0; q < 16; q++) acc2[q] = 0ULL;
#pragma unroll 4
    for (int t = 0; t < TT; t++) {
        ull xp = dupf(x[b*(TT*NN) + t*NN + n]);
#pragma unroll
        for (int q = 0; q < 8; q++) {
            ulonglong2 w = *(const ulonglong2*)&wts[t*DD + q*4];
            ffma2(acc2[q*2+0], xp, w.x);
            ffma2(acc2[q*2+1], xp, w.y);
        }
    }
    float acc[DD];
#pragma unroll
    for (int q = 0; q < 16; q++) {
        float2 f = u2f(acc2[q]);
        acc[q*2+0] = f.x + bis[q*2+0];
        acc[q*2+1] = f.y + bis[q*2+1];
    }

    float ne[DD];
#pragma unroll
    for (int q = 0; q < DD/4; q++) {
        float4 v = *(const float4*)&node_emb[n*DD + q*4];
        ne[q*4+0]=v.x; ne[q*4+1]=v.y; ne[q*4+2]=v.z; ne[q*4+3]=v.w;
    }

    size_t hb = ((size_t)b*NN + n)*CC;
    size_t xb = ((size_t)b*NN + n)*DD;
#pragma unroll
    for (int q = 0; q < DD/4; q++) {
        float4 av = make_float4(acc[q*4], acc[q*4+1], acc[q*4+2], acc[q*4+3]);
        *(float4*)&d_h[hb + 0  + q*4] = av;
        *(float4*)&d_xin[xb + q*4] = av;
        *(float4*)&d_h[hb + 32 + q*4] = make_float4(ne[q*4],  ne[q*4+1],  ne[q*4+2],  ne[q*4+3]);
        *(float4*)&d_h[hb + 64 + q*4] = make_float4(tes[q*4], tes[q*4+1], tes[q*4+2], tes[q*4+3]);
        *(float4*)&d_h[hb + 96 + q*4] = make_float4(wes[q*4], wes[q*4+1], wes[q*4+2], wes[q*4+3]);
    }

    size_t sb = ((size_t)b*NN + n)*PP;
#pragma unroll
    for (int p = 0; p < PP; p++) {
        float s = skb[p];
#pragma unroll
        for (int c = 0; c < DD; c++)
            s += acc[c]*rw1s[p*64 + c] + ne[c]*rw1s[p*64 + 32 + c];
        d_skip[sb + p] = s;
    }

    // ---- phi_q ----
    {
        float np[DD];
#pragma unroll
        for (int q = 0; q < DD/4; q++) {
            float4 v = *(const float4*)&d_np1[n*DD + q*4];
            np[q*4]=v.x; np[q*4+1]=v.y; np[q*4+2]=v.z; np[q*4+3]=v.w;
        }
        float dg = 0.f;
#pragma unroll
        for (int c = 0; c < DD; c++) { float t = np[c]+bp1s[c]; dg += t*t; }
        dg *= 0.5f;
        float mx = -1e30f;
#pragma unroll 4
        for (int q = 0; q < MM/4; q++) {
            float4 v = *(const float4*)&d_nd1[n*MM + q*4];
            mx = fmaxf(mx, fmaxf(fmaxf(v.x + bd1s[q*4+0], v.y + bd1s[q*4+1]),
                                 fmaxf(v.z + bd1s[q*4+2], v.w + bd1s[q*4+3])));
        }
        float sub = dg + mx;
        size_t pb = ((size_t)b*NN + n)*MM;
#pragma unroll
        for (int q = 0; q < MM/4; q++) {
            float4 v = *(const float4*)&d_nd1[n*MM + q*4];
            float4 o;
            o.x = RATIO*(__expf(v.x + bd1s[q*4+0] - sub) + EPSF);
            o.y = RATIO*(__expf(v.y + bd1s[q*4+1] - sub) + EPSF);
            o.z = RATIO*(__expf(v.z + bd1s[q*4+2] - sub) + EPSF);
            o.w = RATIO*(__expf(v.w + bd1s[q*4+3] - sub) + EPSF);
            *(float4*)&d_phiq[pb + q*4] = o;
        }
    }
    // ---- phi_k ----
    {
        float np[DD];
#pragma unroll
        for (int q = 0; q < DD/4; q++) {
            float4 v = *(const float4*)&d_np2[n*DD + q*4];
            np[q*4]=v.x; np[q*4+1]=v.y; np[q*4+2]=v.z; np[q*4+3]=v.w;
        }
        float dg = 0.f;
#pragma unroll
        for (int c = 0; c < DD; c++) { float t = np[c]+bp2s[c]; dg += t*t; }
        dg *= 0.5f;
        float sub = dg + stab2s;
        size_t pb = ((size_t)b*NN + n)*MM;
#pragma unroll
        for (int q = 0; q < MM/4; q++) {
            float4 v = *(const float4*)&d_nd2[n*MM + q*4];
            float4 o;
            o.x = RATIO*(__expf(v.x + bd2s[q*4+0] - sub) + EPSF);
            o.y = RATIO*(__expf(v.y + bd2s[q*4+1] - sub) + EPSF);
            o.z = RATIO*(__expf(v.z + bd2s[q*4+2] - sub) + EPSF);
            o.w = RATIO*(__expf(v.w + bd2s[q*4+3] - sub) + EPSF);
            *(float4*)&d_phik[pb + q*4] = o;
        }
    }
}

// ------------------------- ksum (layer-invariant) -------------------------------
__global__ __launch_bounds__(256) void k_ksum()
{
    int tid = threadIdx.x, b = blockIdx.y;
    int m = tid & 63, sub = tid >> 6;
    float partial = 0.f;
    for (int i = 0; i < 64; i++) {
        int n = blockIdx.x*256 + sub + i*4;
        if (n < NN) partial += d_phik[((size_t)b*NN + n)*MM + m];
    }
    __shared__ float red[256];
    red[tid] = partial; __syncthreads();
    if (tid < 64)
        atomicAdd(&d_ksum[b*MM + tid], red[tid] + red[tid+64] + red[tid+128] + red[tid+192]);
}

// -------- layer-0 fused gate + kv: K=32 gemm + node/batch table adds -------------
#define G0_SMEM 147456
__global__ __launch_bounds__(512) void k_gate0(
    const float* __restrict__ in_w, const float* __restrict__ in_b,
    const float* __restrict__ out_w, const float* __restrict__ out_b)
{
    extern __shared__ float sm0[];
    float* wi_s = sm0;              // [32k][128c]
    float* wo_s = sm0 + 4096;
    float* xs   = sm0 + 8192;       // [128n][32k]
    float* phis = sm0 + 12288;      // [128n][64m]
    float* us   = sm0 + 20480;      // [128n][128c]
    __shared__ float ibs[CC], obs[CC], bgis[CC], bgos[CC];

    int tid = threadIdx.x, b = blockIdx.y;
    for (int j = tid; j < 1024; j += 512) {
        int c = j & 127, kq = j >> 7;
        float4 vi = *(const float4*)&in_w [c*CC + kq*4];
        float4 vo = *(const float4*)&out_w[c*CC + kq*4];
        wi_s[(kq*4+0)*CC + c] = vi.x; wi_s[(kq*4+1)*CC + c] = vi.y;
        wi_s[(kq*4+2)*CC + c] = vi.z; wi_s[(kq*4+3)*CC + c] = vi.w;
        wo_s[(kq*4+0)*CC + c] = vo.x; wo_s[(kq*4+1)*CC + c] = vo.y;
        wo_s[(kq*4+2)*CC + c] = vo.z; wo_s[(kq*4+3)*CC + c] = vo.w;
    }
    if (tid < CC) {
        ibs[tid] = in_b[tid];  obs[tid] = out_b[tid];
        bgis[tid] = d_bgi[b*CC+tid]; bgos[tid] = d_bgo[b*CC+tid];
    }

    int cg = tid & 31, ng = tid >> 5;
    int c4 = cg*4;
    int km8 = (ng & 7) * 8;
    int kc2 = ((ng >> 3) ? 64 : 0) + cg*2;
    ull kvacc[4][2];
#pragma unroll
    for (int mp = 0; mp < 4; mp++) { kvacc[mp][0] = 0ULL; kvacc[mp][1] = 0ULL; }

    const int NT = (NN + 127) / 128;
    for (int tile = blockIdx.x; tile < NT; tile += GX) {
        int n0 = tile*128;
        __syncthreads();
        for (int i = tid; i < 1024; i += 512) {
            int r = i >> 3, kq = (i & 7)*4;
            int n = n0 + r;
            float4 v = (n < NN) ? *(const float4*)&d_xin[((size_t)b*NN + n)*DD + kq]
                                : make_float4(0.f,0.f,0.f,0.f);
            *(float4*)&xs[r*DD + kq] = v;
        }
        for (int i = tid; i < 2048; i += 512) {
            int r = i >> 4, mq = (i & 15)*4;
            int n = n0 + r;
            float4 v = (n < NN) ? *(const float4*)&d_phik[((size_t)b*NN + n)*MM + mq]
                                : make_float4(0.f,0.f,0.f,0.f);
            *(float4*)&phis[r*MM + mq] = v;
        }
        __syncthreads();

        ull ai[8][2], ao[8][2];
#pragma unroll
        for (int j = 0; j < 8; j++) { ai[j][0]=0ULL; ai[j][1]=0ULL; ao[j][0]=0ULL; ao[j][1]=0ULL; }

#pragma unroll 4
        for (int k = 0; k < DD; k++) {
            ulonglong2 wi = *(const ulonglong2*)&wi_s[k*CC + c4];
            ulonglong2 wo = *(const ulonglong2*)&wo_s[k*CC + c4];
#pragma unroll
            for (int j = 0; j < 8; j++) {
                ull hp = dupf(xs[(ng*8+j)*DD + k]);
                ffma2(ai[j][0], hp, wi.x); ffma2(ai[j][1], hp, wi.y);
                ffma2(ao[j][0], hp, wo.x); ffma2(ao[j][1], hp, wo.y);
            }
        }

#pragma unroll
        for (int j = 0; j < 8; j++) {
            int r = ng*8 + j;
            int n = n0 + r;
            float4 u;
            if (n < NN) {
                float4 gi = *(const float4*)&d_ngi[(size_t)n*CC + c4];
                float4 go = *(const float4*)&d_ngo[(size_t)n*CC + c4];
                float2 a0 = u2f(ai[j][0]), a1 = u2f(ai[j][1]);
                float2 o0 = u2f(ao[j][0]), o1 = u2f(ao[j][1]);
                float i0 = a0.x + gi.x + bgis[c4+0] + ibs[c4+0];
                float i1 = a0.y + gi.y + bgis[c4+1] + ibs[c4+1];
                float i2 = a1.x + gi.z + bgis[c4+2] + ibs[c4+2];
                float i3 = a1.y + gi.w + bgis[c4+3] + ibs[c4+3];
                float v0 = o0.x + go.x + bgos[c4+0] + obs[c4+0];
                float v1 = o0.y + go.y + bgos[c4+1] + obs[c4+1];
                float v2 = o1.x + go.z + bgos[c4+2] + obs[c4+2];
                float v3 = o1.y + go.w + bgos[c4+3] + obs[c4+3];
                u.x = v0 / (1.f + __expf(-i0));
                u.y = v1 / (1.f + __expf(-i1));
                u.z = v2 / (1.f + __expf(-i2));
                u.w = v3 / (1.f + __expf(-i3));
            } else {
                u = make_float4(0.f, 0.f, 0.f, 0.f);
            }
            *(float4*)&us[r*CC + c4] = u;
        }
        __syncthreads();

#pragma unroll 2
        for (int n = 0; n < 128; n++) {
            ull u0 = dupf(us[n*CC + kc2 + 0]);
            ull u1 = dupf(us[n*CC + kc2 + 1]);
#pragma unroll
            for (int mp = 0; mp < 4; mp++) {
                ull phv = *(const ull*)&phis[n*MM + km8 + 2*mp];
                ffma2(kvacc[mp][0], phv, u0);
                ffma2(kvacc[mp][1], phv, u1);
            }
        }
    }

    float* kvb = &d_kv[(size_t)b*(MM*CC)];    // layer 0
#pragma unroll
    for (int mp = 0; mp < 4; mp++) {
        float2 f0 = u2f(kvacc[mp][0]);
        float2 f1 = u2f(kvacc[mp][1]);
        int m0 = km8 + 2*mp;
        atomicAdd(&kvb[(m0+0)*CC + kc2 + 0], f0.x);
        atomicAdd(&kvb[(m0+1)*CC + kc2 + 0], f0.y);
        atomicAdd(&kvb[(m0+0)*CC + kc2 + 1], f1.x);
        atomicAdd(&kvb[(m0+1)*CC + kc2 + 1], f1.y);
    }
}

// -------- fused gate + kv (layers 1,2): full K=128 gemm --------------------------
#define GK_SMEM 229376
__global__ __launch_bounds__(512) void k_gatekv(int layer,
    const float* __restrict__ in_w, const float* __restrict__ in_b,
    const float* __restrict__ out_w, const float* __restrict__ out_b)
{
    extern __shared__ float sm[];
    float* wi_s = sm;                    // [128 k][128 c]    64 KB
    float* wo_s = sm + 16384;            //                    64 KB
    float* hs   = sm + 32768;            // h tile, then u tile [128 n][128 c] 64 KB
    float* phis = sm + 49152;            // phik tile [128 n][64 m]            32 KB
    __shared__ float ibs[CC], obs[CC];

    int tid = threadIdx.x, b = blockIdx.y;
    const float* wil = in_w  + layer*CC*CC;
    const float* wol = out_w + layer*CC*CC;
    for (int j = tid; j < 4096; j += 512) {
        int c = j & 127, kq = j >> 7;
        float4 vi = *(const float4*)&wil[c*CC + kq*4];
        float4 vo = *(const float4*)&wol[c*CC + kq*4];
        wi_s[(kq*4+0)*CC + c] = vi.x; wi_s[(kq*4+1)*CC + c] = vi.y;
        wi_s[(kq*4+2)*CC + c] = vi.z; wi_s[(kq*4+3)*CC + c] = vi.w;
        wo_s[(kq*4+0)*CC + c] = vo.x; wo_s[(kq*4+1)*CC + c] = vo.y;
        wo_s[(kq*4+2)*CC + c] = vo.z; wo_s[(kq*4+3)*CC + c] = vo.w;
    }
    if (tid < CC) { ibs[tid] = in_b[layer*CC+tid]; obs[tid] = out_b[layer*CC+tid]; }

    int cg = tid & 31, ng = tid >> 5;
    int c4 = cg*4;
    int km8 = (ng & 7) * 8;
    int kc2 = ((ng >> 3) ? 64 : 0) + cg*2;
    ull kvacc[4][2];
#pragma unroll
    for (int mp = 0; mp < 4; mp++) { kvacc[mp][0] = 0ULL; kvacc[mp][1] = 0ULL; }

    const int NT = (NN + 127) / 128;
    for (int tile = blockIdx.x; tile < NT; tile += GX) {
        int n0 = tile*128;
        __syncthreads();
        for (int i = tid; i < 4096; i += 512) {
            int r = i >> 5, cq = (i & 31)*4;
            int n = n0 + r;
            float4 v = (n < NN) ? *(const float4*)&d_h[((size_t)b*NN + n)*CC + cq]
                                : make_float4(0.f,0.f,0.f,0.f);
            *(float4*)&hs[r*CC + cq] = v;
        }
        for (int i = tid; i < 2048; i += 512) {
            int r = i >> 4, mq = (i & 15)*4;
            int n = n0 + r;
            float4 v = (n < NN) ? *(const float4*)&d_phik[((size_t)b*NN + n)*MM + mq]
                                : make_float4(0.f,0.f,0.f,0.f);
            *(float4*)&phis[r*MM + mq] = v;
        }
        __syncthreads();

        ull ai[8][2], ao[8][2];
#pragma unroll
        for (int j = 0; j < 8; j++) { ai[j][0]=0ULL; ai[j][1]=0ULL; ao[j][0]=0ULL; ao[j][1]=0ULL; }

#pragma unroll 2
        for (int k = 0; k < CC; k++) {
            ulonglong2 wi = *(const ulonglong2*)&wi_s[k*CC + c4];
            ulonglong2 wo = *(const ulonglong2*)&wo_s[k*CC + c4];
#pragma unroll
            for (int j = 0; j < 8; j++) {
                ull hp = dupf(hs[(ng*8+j)*CC + k]);
                ffma2(ai[j][0], hp, wi.x); ffma2(ai[j][1], hp, wi.y);
                ffma2(ao[j][0], hp, wo.x); ffma2(ao[j][1], hp, wo.y);
            }
        }
        __syncthreads();

#pragma unroll
        for (int j = 0; j < 8; j++) {
            int r = ng*8 + j;
            int n = n0 + r;
            float4 u;
            if (n < NN) {
                float2 a0 = u2f(ai[j][0]), a1 = u2f(ai[j][1]);
                float2 o0 = u2f(ao[j][0]), o1 = u2f(ao[j][1]);
                u.x = (o0.x + obs[c4+0]) / (1.f + __expf(-(a0.x + ibs[c4+0])));
                u.y = (o0.y + obs[c4+1]) / (1.f + __expf(-(a0.y + ibs[c4+1])));
                u.z = (o1.x + obs[c4+2]) / (1.f + __expf(-(a1.x + ibs[c4+2])));
                u.w = (o1.y + obs[c4+3]) / (1.f + __expf(-(a1.y + ibs[c4+3])));
            } else {
                u = make_float4(0.f, 0.f, 0.f, 0.f);
            }
            *(float4*)&hs[r*CC + c4] = u;
        }
        __syncthreads();

#pragma unroll 2
        for (int n = 0; n < 128; n++) {
            ull u0 = dupf(hs[n*CC + kc2 + 0]);
            ull u1 = dupf(hs[n*CC + kc2 + 1]);
#pragma unroll
            for (int mp = 0; mp < 4; mp++) {
                ull phv = *(const ull*)&phis[n*MM + km8 + 2*mp];
                ffma2(kvacc[mp][0], phv, u0);
                ffma2(kvacc[mp][1], phv, u1);
            }
        }
    }

    float* kvb = &d_kv[((size_t)layer*BB + b)*(MM*CC)];
#pragma unroll
    for (int mp = 0; mp < 4; mp++) {
        float2 f0 = u2f(kvacc[mp][0]);
        float2 f1 = u2f(kvacc[mp][1]);
        int m0 = km8 + 2*mp;
        atomicAdd(&kvb[(m0+0)*CC + kc2 + 0], f0.x);
        atomicAdd(&kvb[(m0+1)*CC + kc2 + 0], f0.y);
        atomicAdd(&kvb[(m0+0)*CC + kc2 + 1], f1.x);
        atomicAdd(&kvb[(m0+1)*CC + kc2 + 1], f1.y);
    }
}

// ---------- num/den + residual + LN (f32x2), 64-node tiles -----------------------
__global__ __launch_bounds__(256) void k_numln(int layer,
    const float* __restrict__ ln_g, const float* __restrict__ ln_b)
{
    extern __shared__ float kvs[];               // 32 KB dynamic (opted-in)
    __shared__ ull phis2[64*MM];                 // 32 KB
    __shared__ ull ksd[MM];
    __shared__ float lg[CC], lb[CC];
    int tid = threadIdx.x, b = blockIdx.y, chunk = blockIdx.x;
    for (int i = tid*4; i < MM*CC; i += 1024)
        *(float4*)&kvs[i] = *(const float4*)&d_kv[((size_t)layer*BB + b)*(MM*CC) + i];
    if (tid < MM) ksd[tid] = dupf(d_ksum[b*MM+tid]);
    if (tid < CC) { lg[tid] = ln_g[layer*CC+tid]; lb[tid] = ln_b[layer*CC+tid]; }
    __syncthreads();

    int cg = tid & 31, ng = tid >> 5;
    int c4 = cg*4;

    for (int t = 0; t < 8; t++) {
        int n0 = chunk*512 + t*64;
        if (n0 >= NN) break;
        __syncthreads();
        for (int i = tid; i < 1024; i += 256) {
            int r = i >> 4, mq = (i & 15)*4;
            int n = n0 + r;
            float4 v = (n < NN) ? *(const float4*)&d_phiq[((size_t)b*NN+n)*MM + mq]
                                : make_float4(0.f,0.f,0.f,0.f);
            phis2[r*MM+mq+0] = dupf(v.x);
            phis2[r*MM+mq+1] = dupf(v.y);
            phis2[r*MM+mq+2] = dupf(v.z);
            phis2[r*MM+mq+3] = dupf(v.w);
        }
        __syncthreads();

        ull an[8][2], ad2[8];
#pragma unroll
        for (int j = 0; j < 8; j++) { an[j][0]=0ULL; an[j][1]=0ULL; ad2[j]=0ULL; }
#pragma unroll 2
        for (int m = 0; m < MM; m++) {
            ulonglong2 kf = *(const ulonglong2*)&kvs[m*CC + c4];
            ull ks = ksd[m];
#pragma unroll
            for (int j = 0; j < 8; j++) {
                ull pq = phis2[(ng*8+j)*MM + m];
                ffma2(an[j][0], pq, kf.x);
                ffma2(an[j][1], pq, kf.y);
                ffma2(ad2[j],   pq, ks);
            }
        }
#pragma unroll
        for (int j = 0; j < 8; j++) {
            int n = n0 + ng*8 + j;
            if (n >= NN) continue;   // warp-uniform
            size_t base = ((size_t)b*NN + n)*CC + c4;
            float4 hv = *(const float4*)&d_h[base];
            float2 n0f = u2f(an[j][0]), n1f = u2f(an[j][1]);
            float inv = 1.f / u2f(ad2[j]).x;
            float v0 = n0f.x*inv + hv.x;
            float v1 = n0f.y*inv + hv.y;
            float v2 = n1f.x*inv + hv.z;
            float v3 = n1f.y*inv + hv.w;
            float s1 = v0+v1+v2+v3;
            float s2 = v0*v0+v1*v1+v2*v2+v3*v3;
#pragma unroll
            for (int o = 16; o >= 1; o >>= 1) {
                s1 += __shfl_xor_sync(0xffffffffu, s1, o);
                s2 += __shfl_xor_sync(0xffffffffu, s2, o);
            }
            float mu = s1*(1.f/128.f);
            float var = s2*(1.f/128.f) - mu*mu;
            float rs = rsqrtf(var + 1e-5f);
            float4 o4;
            o4.x = (v0-mu)*rs*lg[c4+0] + lb[c4+0];
            o4.y = (v1-mu)*rs*lg[c4+1] + lb[c4+1];
            o4.z = (v2-mu)*rs*lg[c4+2] + lb[c4+2];
            o4.w = (v3-mu)*rs*lg[c4+3] + lb[c4+3];
            *(float4*)&d_h[base] = o4;
        }
    }
}

// ------------------------- final regression --------------------------------------
__global__ __launch_bounds__(256) void k_out(
    const float* __restrict__ reg_w, const float* __restrict__ reg_b,
    float* __restrict__ out)
{
    __shared__ float rw2s[PP*CC];
    __shared__ float rbs[PP];
    int tid = threadIdx.x, b = blockIdx.y;
    for (int i = tid; i < PP*CC; i += 256) {
        int p = i >> 7, c = i & 127;
        rw2s[i] = reg_w[p*(2*CC) + CC + c];
    }
    if (tid < PP) rbs[tid] = reg_b[tid];
    __syncthreads();
    int n = blockIdx.x*256 + tid;
    if (n >= NN) return;
    float a[PP];
    size_t sb = ((size_t)b*NN + n)*PP;
#pragma unroll
    for (int p = 0; p < PP; p++) a[p] = d_skip[sb + p] + rbs[p];
    size_t hb = ((size_t)b*NN + n)*CC;
#pragma unroll 4
    for (int q = 0; q < CC/4; q++) {
        float4 hv = *(const float4*)&d_h[hb + q*4];
#pragma unroll
        for (int p = 0; p < PP; p++) {
            a[p] += hv.x*rw2s[p*CC + q*4+0] + hv.y*rw2s[p*CC + q*4+1]
                  + hv.z*rw2s[p*CC + q*4+2] + hv.w*rw2s[p*CC + q*4+3];
        }
    }
#pragma unroll
    for (int p = 0; p < PP; p++)
        out[(b*PP + p)*NN + n] = a[p];
}

// ------------------------- launch ------------------------------------------------
extern "C" void kernel_launch(void* const* d_in, const int* in_sizes, int n_in,
                              void* d_out, int out_size)
{
    const float* x        = (const float*)d_in[0];
    const float* x_mark   = (const float*)d_in[1];
    const float* node_emb = (const float*)d_in[2];
    const float* time_tab = (const float*)d_in[3];
    const float* week_tab = (const float*)d_in[4];
    const float* input_w  = (const float*)d_in[5];
    const float* input_b  = (const float*)d_in[6];
    const float* w1_w     = (const float*)d_in[7];
    const float* w1_b     = (const float*)d_in[8];
    const float* w2_w     = (const float*)d_in[9];
    const float* w2_b     = (const float*)d_in[10];
    const float* in_w     = (const float*)d_in[11];
    const float* in_b     = (const float*)d_in[12];
    const float* out_w    = (const float*)d_in[13];
    const float* out_b    = (const float*)d_in[14];
    const float* ln_g     = (const float*)d_in[15];
    const float* ln_b     = (const float*)d_in[16];
    const float* reg_w    = (const float*)d_in[17];
    const float* reg_b    = (const float*)d_in[18];
    const float* proj     = (const float*)d_in[19];
    float* out = (float*)d_out;

    cudaFuncSetAttribute(k_gate0,  cudaFuncAttributeMaxDynamicSharedMemorySize, G0_SMEM);
    cudaFuncSetAttribute(k_gatekv, cudaFuncAttributeMaxDynamicSharedMemorySize, GK_SMEM);
    cudaFuncSetAttribute(k_numln,  cudaFuncAttributeMaxDynamicSharedMemorySize, 32768);

    k_batch<<<1, 256>>>(x_mark, time_tab, week_tab, w1_w, w1_b, w2_w, w2_b,
                        input_w, input_b, proj, reg_w, in_w, out_w);
    k_node<<<(NN+127)/128, 128>>>(node_emb, w1_w, w2_w, proj, in_w, out_w);
    k_embed<<<dim3((NN+255)/256, BB), 256>>>(x, node_emb, input_w, reg_w);
    // layer-0 fused gate+kv is the 4th launch -> profiled by ncu
    k_gate0<<<dim3(GX, BB), 512, G0_SMEM>>>(in_w, in_b, out_w, out_b);
    k_ksum<<<dim3((NN+255)/256, BB), 256>>>();
    k_numln<<<dim3(40, BB), 256, 32768>>>(0, ln_g, ln_b);
    for (int l = 1; l < 3; l++) {
        k_gatekv<<<dim3(GX, BB), 512, GK_SMEM>>>(l, in_w, in_b, out_w, out_b);
        k_numln<<<dim3(40, BB), 256, 32768>>>(l, ln_g, ln_b);
    }
    k_out<<<dim3((NN+255)/256, BB), 256>>>(reg_w, reg_b, out);
}

// round 16
// speedup vs baseline: 1.1314x; 1.0718x over previous
#include <cuda_runtime.h>
#include <math.h>
#include <stdint.h>

#define BB 8
#define TT 96
#define NN 20000
#define PP 12
#define DD 32
#define CC 128
#define MM 64
#define GX 18   // gate grid.x (144 CTAs, 1/SM)
// 2 * 32^-0.25  (inv_sqrt_tau * d^-1/4)
#define SC 0.8408964152537145f
#define RATIO 0.125f
#define EPSF 1e-6f

typedef unsigned long long ull;

// ---- packed f32x2 helpers ----------------------------------------------------
__device__ __forceinline__ void ffma2(ull& d, ull a, ull b) {
    asm("fma.rn.f32x2 %0, %1, %2, %0;" : "+l"(d) : "l"(a), "l"(b));
}
__device__ __forceinline__ ull dupf(float v) {
    ull r; asm("mov.b64 %0, {%1, %1};" : "=l"(r) : "f"(v)); return r;
}
__device__ __forceinline__ ull pk2(float lo, float hi) {
    ull r; asm("mov.b64 %0, {%1, %2};" : "=l"(r) : "f"(lo), "f"(hi)); return r;
}
__device__ __forceinline__ float2 u2f(ull v) {
    float2 f; asm("mov.b64 {%0, %1}, %2;" : "=f"(f.x), "=f"(f.y) : "l"(v)); return f;
}

// ---- ordered-uint encoding for float atomicMax --------------------------------
__device__ __forceinline__ unsigned fenc(float f) {
    unsigned b = __float_as_uint(f);
    return (b & 0x80000000u) ? ~b : (b | 0x80000000u);
}
__device__ __forceinline__ float fdec(unsigned e) {
    unsigned b = (e & 0x80000000u) ? (e ^ 0x80000000u) : ~e;
    return __uint_as_float(b);
}

// ------------------------- static device scratch -----------------------------
__device__ float d_h[BB*NN*CC];
__device__ float d_xin[BB*NN*DD];
__device__ float d_ngi[NN*CC];
__device__ float d_ngo[NN*CC];
__device__ float d_bgi[BB*CC];
__device__ float d_bgo[BB*CC];
__device__ float d_phiq[BB*NN*MM];
__device__ float d_phik[BB*NN*MM];
__device__ float d_skip[BB*NN*PP];
__device__ float d_np1[NN*DD], d_np2[NN*DD];
__device__ float d_nd1[NN*MM], d_nd2[NN*MM];
__device__ unsigned d_colenc[MM];
__device__ float d_bp1[BB*DD], d_bp2[BB*DD];
__device__ float d_bd1[BB*MM], d_bd2[BB*MM];
__device__ float d_biasin[BB*DD];
__device__ float d_te[BB*DD], d_we[BB*DD];
__device__ float d_skipb[BB*PP];
__device__ float d_kv[3*BB*MM*CC];
__device__ float d_ksum[BB*MM];

// ------------------------- per-batch constants --------------------------------
__global__ __launch_bounds__(256) void k_batch(
    const float* __restrict__ x_mark, const float* __restrict__ time_tab,
    const float* __restrict__ week_tab,
    const float* __restrict__ w1_w, const float* __restrict__ w1_b,
    const float* __restrict__ w2_w, const float* __restrict__ w2_b,
    const float* __restrict__ input_w, const float* __restrict__ input_b,
    const float* __restrict__ proj, const float* __restrict__ reg_w,
    const float* __restrict__ in_w, const float* __restrict__ out_w)
{
    __shared__ float bp1s[BB*DD], bp2s[BB*DD];
    __shared__ float tesh[BB*DD], wesh[BB*DD];
    __shared__ int tods[BB], dows[BB];
    int tid = threadIdx.x;
    if (tid < MM) d_colenc[tid] = 0u;
    d_ksum[tid] = 0.f;
    d_ksum[256 + tid] = 0.f;
    if (tid < BB) {
        float v0 = x_mark[tid*TT*2 + (TT-1)*2 + 0];
        float v1 = x_mark[tid*TT*2 + (TT-1)*2 + 1];
        int ti = (int)(v0 * (float)TT); ti = ti < 0 ? 0 : (ti > TT-1 ? TT-1 : ti);
        int di = (int)(v1 * 7.0f);      di = di < 0 ? 0 : (di > 6 ? 6 : di);
        tods[tid] = ti; dows[tid] = di;
    }
    __syncthreads();
    int b = tid >> 5, c = tid & 31;
    float te = time_tab[tods[b]*DD + c];
    float we = week_tab[dows[b]*DD + c];
    d_te[b*DD+c] = te; d_we[b*DD+c] = we;
    tesh[b*DD+c] = te; wesh[b*DD+c] = we;

    float a1 = w1_b[c], a2 = w2_b[c];
    for (int g = 0; g < DD; g++) {
        float tg = time_tab[tods[b]*DD+g], wg = week_tab[dows[b]*DD+g];
        a1 += tg * w1_w[c*(3*DD) + DD + g] + wg * w1_w[c*(3*DD) + 2*DD + g];
        a2 += tg * w2_w[c*(3*DD) + DD + g] + wg * w2_w[c*(3*DD) + 2*DD + g];
    }
    a1 *= SC; a2 *= SC;
    d_bp1[b*DD+c] = a1; d_bp2[b*DD+c] = a2;
    bp1s[b*DD+c] = a1;  bp2s[b*DD+c] = a2;

    float bi = input_b[c];
    for (int t = 0; t < TT; t++) {
        bi += x_mark[b*TT*2 + t*2 + 0] * input_w[c*(3*TT) + TT + t]
            + x_mark[b*TT*2 + t*2 + 1] * input_w[c*(3*TT) + 2*TT + t];
    }
    d_biasin[b*DD+c] = bi;

    if (c < PP) {
        float s = 0.f;
        for (int g = 0; g < DD; g++)
            s += time_tab[tods[b]*DD+g] * reg_w[c*(2*CC) + 2*DD + g]
               + week_tab[dows[b]*DD+g] * reg_w[c*(2*CC) + 3*DD + g];
        d_skipb[b*PP + c] = s;
    }
    __syncthreads();
    for (int mm = c; mm < MM; mm += 32) {
        float s1 = 0.f, s2 = 0.f;
        for (int cc = 0; cc < DD; cc++) {
            float p = proj[mm*DD + cc];
            s1 += bp1s[b*DD+cc] * p; s2 += bp2s[b*DD+cc] * p;
        }
        d_bd1[b*MM+mm] = s1; d_bd2[b*MM+mm] = s2;
    }
    // per-batch constant part of layer-0 gate gemms (te,we quarters)
    for (int cc = c; cc < CC; cc += 32) {
        float si = 0.f, so = 0.f;
        for (int g = 0; g < DD; g++) {
            float tg = tesh[b*DD+g], wg = wesh[b*DD+g];
            si += tg * in_w [cc*CC + 64 + g] + wg * in_w [cc*CC + 96 + g];
            so += tg * out_w[cc*CC + 64 + g] + wg * out_w[cc*CC + 96 + g];
        }
        d_bgi[b*CC+cc] = si; d_bgo[b*CC+cc] = so;
    }
}

// -------------- per-node tables (+ colmax, + kv zero, + layer-0 node-gate) ------
__global__ __launch_bounds__(128) void k_node(
    const float* __restrict__ node_emb, const float* __restrict__ w1_w,
    const float* __restrict__ w2_w, const float* __restrict__ proj,
    const float* __restrict__ in_w, const float* __restrict__ out_w)
{
    __shared__ float w1s[DD*DD], w2s[DD*DD], ps[MM*DD];
    __shared__ float wgi[CC*DD], wgo[CC*DD];
    int tid = threadIdx.x;
    {
        int gid = blockIdx.x*128 + tid;
        for (int i = gid; i < (3*BB*MM*CC)/4; i += 20096)
            *(float4*)&d_kv[i*4] = make_float4(0.f,0.f,0.f,0.f);
    }
    for (int i = tid; i < DD*DD; i += 128) {
        int c = i >> 5, g = i & 31;
        w1s[i] = w1_w[c*(3*DD) + g];
        w2s[i] = w2_w[c*(3*DD) + g];
    }
    for (int i = tid; i < MM*DD; i += 128) ps[i] = proj[i];
    for (int i = tid; i < CC*DD; i += 128) {
        int c = i >> 5, g = i & 31;
        wgi[i] = in_w [c*CC + DD + g];
        wgo[i] = out_w[c*CC + DD + g];
    }
    __syncthreads();
    int n = blockIdx.x * 128 + tid;
    if (n >= NN) return;
    float e[DD];
#pragma unroll
    for (int q = 0; q < DD/4; q++) {
        float4 v = *(const float4*)&node_emb[n*DD + q*4];
        e[q*4+0]=v.x; e[q*4+1]=v.y; e[q*4+2]=v.z; e[q*4+3]=v.w;
    }
    float np1[DD], np2[DD];
#pragma unroll 4
    for (int c = 0; c < DD; c++) {
        float s1 = 0.f, s2 = 0.f;
#pragma unroll
        for (int g = 0; g < DD; g++) { s1 += e[g]*w1s[c*DD+g]; s2 += e[g]*w2s[c*DD+g]; }
        np1[c] = s1 * SC; np2[c] = s2 * SC;
        d_np1[n*DD+c] = np1[c]; d_np2[n*DD+c] = np2[c];
    }
#pragma unroll 2
    for (int m = 0; m < MM; m++) {
        float s1 = 0.f, s2 = 0.f;
#pragma unroll
        for (int c = 0; c < DD; c++) { float p = ps[m*DD+c]; s1 += np1[c]*p; s2 += np2[c]*p; }
        d_nd1[n*MM+m] = s1; d_nd2[n*MM+m] = s2;
        float mx = s2;
#pragma unroll
        for (int o = 16; o >= 1; o >>= 1)
            mx = fmaxf(mx, __shfl_xor_sync(0xffffffffu, mx, o));
        if ((tid & 31) == 0) atomicMax(&d_colenc[m], fenc(mx));
    }
#pragma unroll 2
    for (int c = 0; c < CC; c++) {
        float s1 = 0.f, s2 = 0.f;
#pragma unroll
        for (int g = 0; g < DD; g++) { s1 += e[g]*wgi[c*DD+g]; s2 += e[g]*wgo[c*DD+g]; }
        d_ngi[(size_t)n*CC + c] = s1;
        d_ngo[(size_t)n*CC + c] = s2;
    }
}

// ------------------------- embedding + phi + h0 + skip --------------------------
__global__ __launch_bounds__(256) void k_embed(
    const float* __restrict__ x, const float* __restrict__ node_emb,
    const float* __restrict__ input_w, const float* __restrict__ reg_w)
{
    __shared__ __align__(16) float wts[TT*DD];
    __shared__ __align__(8) float rw1s[PP*2*DD];
    __shared__ float bis[DD], bp1s[DD], bp2s[DD], tes[DD], wes[DD];
    __shared__ float bd1s[MM], bd2s[MM], cmax[MM];
    __shared__ float skb[PP];
    __shared__ float stab2s;

    int b = blockIdx.y; int tid = threadIdx.x;
    for (int i = tid; i < TT*DD; i += 256) {
        int t = i >> 5, c = i & 31;
        wts[i] = input_w[c*(3*TT) + t];
    }
    for (int i = tid; i < PP*2*DD; i += 256) {
        int p = i >> 6, k = i & 63;
        rw1s[i] = reg_w[p*(2*CC) + k];
    }
    if (tid < DD) {
        bis[tid]  = d_biasin[b*DD+tid];
        bp1s[tid] = d_bp1[b*DD+tid]; bp2s[tid] = d_bp2[b*DD+tid];
        tes[tid]  = d_te[b*DD+tid];  wes[tid]  = d_we[b*DD+tid];
    }
    if (tid < MM) {
        bd1s[tid] = d_bd1[b*MM+tid]; bd2s[tid] = d_bd2[b*MM+tid];
        cmax[tid] = fdec(d_colenc[tid]) + d_bd2[b*MM+tid];
    }
    if (tid < PP) skb[tid] = d_skipb[b*PP+tid];
    __syncthreads();
    if (tid == 0) {
        float mx = -1e30f;
        for (int i = 0; i < MM; i++) mx = fmaxf(mx, cmax[i]);
        stab2s = mx;
    }
    __syncthreads();

    int n = blockIdx.x*256 + tid;
    if (n >= NN) return;

    ull acc2[16];
#pragma unroll
    for (int q = 0; q < 16; q++) acc2[q] = 0ULL;
#pragma unroll 4
    for (int t = 0; t < TT; t++) {
        ull xp = dupf(x[b*(TT*NN) + t*NN + n]);
#pragma unroll
        for (int q = 0; q < 8; q++) {
            ulonglong2 w = *(const ulonglong2*)&wts[t*DD + q*4];
            ffma2(acc2[q*2+0], xp, w.x);
            ffma2(acc2[q*2+1], xp, w.y);
        }
    }
    float acc[DD];
#pragma unroll
    for (int q = 0; q < 16; q++) {
        float2 f = u2f(acc2[q]);
        acc[q*2+0] = f.x + bis[q*2+0];
        acc[q*2+1] = f.y + bis[q*2+1];
    }

    float ne[DD];
#pragma unroll
    for (int q = 0; q < DD/4; q++) {
        float4 v = *(const float4*)&node_emb[n*DD + q*4];
        ne[q*4+0]=v.x; ne[q*4+1]=v.y; ne[q*4+2]=v.z; ne[q*4+3]=v.w;
    }

    size_t hb = ((size_t)b*NN + n)*CC;
    size_t xb = ((size_t)b*NN + n)*DD;
#pragma unroll
    for (int q = 0; q < DD/4; q++) {
        float4 av = make_float4(acc[q*4], acc[q*4+1], acc[q*4+2], acc[q*4+3]);
        *(float4*)&d_h[hb + 0  + q*4] = av;
        *(float4*)&d_xin[xb + q*4] = av;
        *(float4*)&d_h[hb + 32 + q*4] = make_float4(ne[q*4],  ne[q*4+1],  ne[q*4+2],  ne[q*4+3]);
        *(float4*)&d_h[hb + 64 + q*4] = make_float4(tes[q*4], tes[q*4+1], tes[q*4+2], tes[q*4+3]);
        *(float4*)&d_h[hb + 96 + q*4] = make_float4(wes[q*4], wes[q*4+1], wes[q*4+2], wes[q*4+3]);
    }

    // ---- skip regression (packed f32x2) ----
    {
        ull ap[DD/2];            // 16 pairs: acc then ne
#pragma unroll
        for (int q = 0; q < DD/2/2; q++) {
            ap[q]            = pk2(acc[q*2], acc[q*2+1]);
            ap[q + DD/4]     = pk2(acc[DD/2 + q*2], acc[DD/2 + q*2+1]);
        }
        // note: layout above packs acc[0..31] into ap[0..15] sequentially
        // (first 8 pairs from acc[0..15], next 8 from acc[16..31])
        ull np[DD/2];
#pragma unroll
        for (int q = 0; q < DD/2; q++) np[q] = pk2(ne[q*2], ne[q*2+1]);
        size_t sb = ((size_t)b*NN + n)*PP;
#pragma unroll
        for (int p = 0; p < PP; p++) {
            ull s2a = 0ULL;
#pragma unroll
            for (int q = 0; q < DD/2; q++) {
                // acc pair q covers channels 2q,2q+1 — recompute mapping directly
                ;
            }
            // direct packed accumulation
            s2a = 0ULL;
#pragma unroll
            for (int q = 0; q < DD/4; q++) {
                ffma2(s2a, pk2(acc[q*4+0], acc[q*4+1]), *(const ull*)&rw1s[p*64 + q*4]);
                ffma2(s2a, pk2(acc[q*4+2], acc[q*4+3]), *(const ull*)&rw1s[p*64 + q*4+2]);
                ffma2(s2a, np[q*2+0], *(const ull*)&rw1s[p*64 + 32 + q*4]);
                ffma2(s2a, np[q*2+1], *(const ull*)&rw1s[p*64 + 32 + q*4+2]);
            }
            float2 f = u2f(s2a);
            d_skip[sb + p] = skb[p] + f.x + f.y;
        }
    }

    // ---- phi_q ----
    {
        float np[DD];
#pragma unroll
        for (int q = 0; q < DD/4; q++) {
            float4 v = *(const float4*)&d_np1[n*DD + q*4];
            np[q*4]=v.x; np[q*4+1]=v.y; np[q*4+2]=v.z; np[q*4+3]=v.w;
        }
        float dg = 0.f;
#pragma unroll
        for (int c = 0; c < DD; c++) { float t = np[c]+bp1s[c]; dg += t*t; }
        dg *= 0.5f;
        float mx = -1e30f;
#pragma unroll 4
        for (int q = 0; q < MM/4; q++) {
            float4 v = *(const float4*)&d_nd1[n*MM + q*4];
            mx = fmaxf(mx, fmaxf(fmaxf(v.x + bd1s[q*4+0], v.y + bd1s[q*4+1]),
                                 fmaxf(v.z + bd1s[q*4+2], v.w + bd1s[q*4+3])));
        }
        float sub = dg + mx;
        size_t pb = ((size_t)b*NN + n)*MM;
#pragma unroll
        for (int q = 0; q < MM/4; q++) {
            float4 v = *(const float4*)&d_nd1[n*MM + q*4];
            float4 o;
            o.x = RATIO*(__expf(v.x + bd1s[q*4+0] - sub) + EPSF);
            o.y = RATIO*(__expf(v.y + bd1s[q*4+1] - sub) + EPSF);
            o.z = RATIO*(__expf(v.z + bd1s[q*4+2] - sub) + EPSF);
            o.w = RATIO*(__expf(v.w + bd1s[q*4+3] - sub) + EPSF);
            *(float4*)&d_phiq[pb + q*4] = o;
        }
    }
    // ---- phi_k ----
    {
        float np[DD];
#pragma unroll
        for (int q = 0; q < DD/4; q++) {
            float4 v = *(const float4*)&d_np2[n*DD + q*4];
            np[q*4]=v.x; np[q*4+1]=v.y; np[q*4+2]=v.z; np[q*4+3]=v.w;
        }
        float dg = 0.f;
#pragma unroll
        for (int c = 0; c < DD; c++) { float t = np[c]+bp2s[c]; dg += t*t; }
        dg *= 0.5f;
        float sub = dg + stab2s;
        size_t pb = ((size_t)b*NN + n)*MM;
#pragma unroll
        for (int q = 0; q < MM/4; q++) {
            float4 v = *(const float4*)&d_nd2[n*MM + q*4];
            float4 o;
            o.x = RATIO*(__expf(v.x + bd2s[q*4+0] - sub) + EPSF);
            o.y = RATIO*(__expf(v.y + bd2s[q*4+1] - sub) + EPSF);
            o.z = RATIO*(__expf(v.z + bd2s[q*4+2] - sub) + EPSF);
            o.w = RATIO*(__expf(v.w + bd2s[q*4+3] - sub) + EPSF);
            *(float4*)&d_phik[pb + q*4] = o;
        }
    }
}

// ------------------------- ksum (layer-invariant) -------------------------------
__global__ __launch_bounds__(256) void k_ksum()
{
    int tid = threadIdx.x, b = blockIdx.y;
    int m = tid & 63, sub = tid >> 6;
    float partial = 0.f;
    for (int i = 0; i < 64; i++) {
        int n = blockIdx.x*256 + sub + i*4;
        if (n < NN) partial += d_phik[((size_t)b*NN + n)*MM + m];
    }
    __shared__ float red[256];
    red[tid] = partial; __syncthreads();
    if (tid < 64)
        atomicAdd(&d_ksum[b*MM + tid], red[tid] + red[tid+64] + red[tid+128] + red[tid+192]);
}

// -------- layer-0 fused gate + kv: K=32 gemm + node/batch table adds -------------
#define G0_SMEM 147456
__global__ __launch_bounds__(512) void k_gate0(
    const float* __restrict__ in_w, const float* __restrict__ in_b,
    const float* __restrict__ out_w, const float* __restrict__ out_b)
{
    extern __shared__ float sm0[];
    float* wi_s = sm0;              // [32k][128c]
    float* wo_s = sm0 + 4096;
    float* xs   = sm0 + 8192;       // [128n][32k]
    float* phis = sm0 + 12288;      // [128n][64m]
    float* us   = sm0 + 20480;      // [128n][128c]
    __shared__ float ibs[CC], obs[CC], bgis[CC], bgos[CC];

    int tid = threadIdx.x, b = blockIdx.y;
    for (int j = tid; j < 1024; j += 512) {
        int c = j & 127, kq = j >> 7;
        float4 vi = *(const float4*)&in_w [c*CC + kq*4];
        float4 vo = *(const float4*)&out_w[c*CC + kq*4];
        wi_s[(kq*4+0)*CC + c] = vi.x; wi_s[(kq*4+1)*CC + c] = vi.y;
        wi_s[(kq*4+2)*CC + c] = vi.z; wi_s[(kq*4+3)*CC + c] = vi.w;
        wo_s[(kq*4+0)*CC + c] = vo.x; wo_s[(kq*4+1)*CC + c] = vo.y;
        wo_s[(kq*4+2)*CC + c] = vo.z; wo_s[(kq*4+3)*CC + c] = vo.w;
    }
    if (tid < CC) {
        ibs[tid] = in_b[tid];  obs[tid] = out_b[tid];
        bgis[tid] = d_bgi[b*CC+tid]; bgos[tid] = d_bgo[b*CC+tid];
    }

    int cg = tid & 31, ng = tid >> 5;
    int c4 = cg*4;
    int km8 = (ng & 7) * 8;
    int kc2 = ((ng >> 3) ? 64 : 0) + cg*2;
    ull kvacc[4][2];
#pragma unroll
    for (int mp = 0; mp < 4; mp++) { kvacc[mp][0] = 0ULL; kvacc[mp][1] = 0ULL; }

    const int NT = (NN + 127) / 128;
    for (int tile = blockIdx.x; tile < NT; tile += GX) {
        int n0 = tile*128;
        __syncthreads();
        for (int i = tid; i < 1024; i += 512) {
            int r = i >> 3, kq = (i & 7)*4;
            int n = n0 + r;
            float4 v = (n < NN) ? *(const float4*)&d_xin[((size_t)b*NN + n)*DD + kq]
                                : make_float4(0.f,0.f,0.f,0.f);
            *(float4*)&xs[r*DD + kq] = v;
        }
        for (int i = tid; i < 2048; i += 512) {
            int r = i >> 4, mq = (i & 15)*4;
            int n = n0 + r;
            float4 v = (n < NN) ? *(const float4*)&d_phik[((size_t)b*NN + n)*MM + mq]
                                : make_float4(0.f,0.f,0.f,0.f);
            *(float4*)&phis[r*MM + mq] = v;
        }
        __syncthreads();

        ull ai[8][2], ao[8][2];
#pragma unroll
        for (int j = 0; j < 8; j++) { ai[j][0]=0ULL; ai[j][1]=0ULL; ao[j][0]=0ULL; ao[j][1]=0ULL; }

#pragma unroll 4
        for (int k = 0; k < DD; k++) {
            ulonglong2 wi = *(const ulonglong2*)&wi_s[k*CC + c4];
            ulonglong2 wo = *(const ulonglong2*)&wo_s[k*CC + c4];
#pragma unroll
            for (int j = 0; j < 8; j++) {
                ull hp = dupf(xs[(ng*8+j)*DD + k]);
                ffma2(ai[j][0], hp, wi.x); ffma2(ai[j][1], hp, wi.y);
                ffma2(ao[j][0], hp, wo.x); ffma2(ao[j][1], hp, wo.y);
            }
        }

#pragma unroll
        for (int j = 0; j < 8; j++) {
            int r = ng*8 + j;
            int n = n0 + r;
            float4 u;
            if (n < NN) {
                float4 gi = *(const float4*)&d_ngi[(size_t)n*CC + c4];
                float4 go = *(const float4*)&d_ngo[(size_t)n*CC + c4];
                float2 a0 = u2f(ai[j][0]), a1 = u2f(ai[j][1]);
                float2 o0 = u2f(ao[j][0]), o1 = u2f(ao[j][1]);
                float i0 = a0.x + gi.x + bgis[c4+0] + ibs[c4+0];
                float i1 = a0.y + gi.y + bgis[c4+1] + ibs[c4+1];
                float i2 = a1.x + gi.z + bgis[c4+2] + ibs[c4+2];
                float i3 = a1.y + gi.w + bgis[c4+3] + ibs[c4+3];
                float v0 = o0.x + go.x + bgos[c4+0] + obs[c4+0];
                float v1 = o0.y + go.y + bgos[c4+1] + obs[c4+1];
                float v2 = o1.x + go.z + bgos[c4+2] + obs[c4+2];
                float v3 = o1.y + go.w + bgos[c4+3] + obs[c4+3];
                u.x = v0 / (1.f + __expf(-i0));
                u.y = v1 / (1.f + __expf(-i1));
                u.z = v2 / (1.f + __expf(-i2));
                u.w = v3 / (1.f + __expf(-i3));
            } else {
                u = make_float4(0.f, 0.f, 0.f, 0.f);
            }
            *(float4*)&us[r*CC + c4] = u;
        }
        __syncthreads();

#pragma unroll 2
        for (int n = 0; n < 128; n++) {
            ull u0 = dupf(us[n*CC + kc2 + 0]);
            ull u1 = dupf(us[n*CC + kc2 + 1]);
#pragma unroll
            for (int mp = 0; mp < 4; mp++) {
                ull phv = *(const ull*)&phis[n*MM + km8 + 2*mp];
                ffma2(kvacc[mp][0], phv, u0);
                ffma2(kvacc[mp][1], phv, u1);
            }
        }
    }

    float* kvb = &d_kv[(size_t)b*(MM*CC)];    // layer 0
#pragma unroll
    for (int mp = 0; mp < 4; mp++) {
        float2 f0 = u2f(kvacc[mp][0]);
        float2 f1 = u2f(kvacc[mp][1]);
        int m0 = km8 + 2*mp;
        atomicAdd(&kvb[(m0+0)*CC + kc2 + 0], f0.x);
        atomicAdd(&kvb[(m0+1)*CC + kc2 + 0], f0.y);
        atomicAdd(&kvb[(m0+0)*CC + kc2 + 1], f1.x);
        atomicAdd(&kvb[(m0+1)*CC + kc2 + 1], f1.y);
    }
}

// -------- fused gate + kv (layers 1,2): full K=128 gemm --------------------------
#define GK_SMEM 229376
__global__ __launch_bounds__(512) void k_gatekv(int layer,
    const float* __restrict__ in_w, const float* __restrict__ in_b,
    const float* __restrict__ out_w, const float* __restrict__ out_b)
{
    extern __shared__ float sm[];
    float* wi_s = sm;                    // [128 k][128 c]    64 KB
    float* wo_s = sm + 16384;            //                    64 KB
    float* hs   = sm + 32768;            // h tile, then u tile [128 n][128 c] 64 KB
    float* phis = sm + 49152;            // phik tile [128 n][64 m]            32 KB
    __shared__ float ibs[CC], obs[CC];

    int tid = threadIdx.x, b = blockIdx.y;
    const float* wil = in_w  + layer*CC*CC;
    const float* wol = out_w + layer*CC*CC;
    for (int j = tid; j < 4096; j += 512) {
        int c = j & 127, kq = j >> 7;
        float4 vi = *(const float4*)&wil[c*CC + kq*4];
        float4 vo = *(const float4*)&wol[c*CC + kq*4];
        wi_s[(kq*4+0)*CC + c] = vi.x; wi_s[(kq*4+1)*CC + c] = vi.y;
        wi_s[(kq*4+2)*CC + c] = vi.z; wi_s[(kq*4+3)*CC + c] = vi.w;
        wo_s[(kq*4+0)*CC + c] = vo.x; wo_s[(kq*4+1)*CC + c] = vo.y;
        wo_s[(kq*4+2)*CC + c] = vo.z; wo_s[(kq*4+3)*CC + c] = vo.w;
    }
    if (tid < CC) { ibs[tid] = in_b[layer*CC+tid]; obs[tid] = out_b[layer*CC+tid]; }

    int cg = tid & 31, ng = tid >> 5;
    int c4 = cg*4;
    int km8 = (ng & 7) * 8;
    int kc2 = ((ng >> 3) ? 64 : 0) + cg*2;
    ull kvacc[4][2];
#pragma unroll
    for (int mp = 0; mp < 4; mp++) { kvacc[mp][0] = 0ULL; kvacc[mp][1] = 0ULL; }

    const int NT = (NN + 127) / 128;
    for (int tile = blockIdx.x; tile < NT; tile += GX) {
        int n0 = tile*128;
        __syncthreads();
        for (int i = tid; i < 4096; i += 512) {
            int r = i >> 5, cq = (i & 31)*4;
            int n = n0 + r;
            float4 v = (n < NN) ? *(const float4*)&d_h[((size_t)b*NN + n)*CC + cq]
                                : make_float4(0.f,0.f,0.f,0.f);
            *(float4*)&hs[r*CC + cq] = v;
        }
        for (int i = tid; i < 2048; i += 512) {
            int r = i >> 4, mq = (i & 15)*4;
            int n = n0 + r;
            float4 v = (n < NN) ? *(const float4*)&d_phik[((size_t)b*NN + n)*MM + mq]
                                : make_float4(0.f,0.f,0.f,0.f);
            *(float4*)&phis[r*MM + mq] = v;
        }
        __syncthreads();

        ull ai[8][2], ao[8][2];
#pragma unroll
        for (int j = 0; j < 8; j++) { ai[j][0]=0ULL; ai[j][1]=0ULL; ao[j][0]=0ULL; ao[j][1]=0ULL; }

#pragma unroll 2
        for (int k = 0; k < CC; k++) {
            ulonglong2 wi = *(const ulonglong2*)&wi_s[k*CC + c4];
            ulonglong2 wo = *(const ulonglong2*)&wo_s[k*CC + c4];
#pragma unroll
            for (int j = 0; j < 8; j++) {
                ull hp = dupf(hs[(ng*8+j)*CC + k]);
                ffma2(ai[j][0], hp, wi.x); ffma2(ai[j][1], hp, wi.y);
                ffma2(ao[j][0], hp, wo.x); ffma2(ao[j][1], hp, wo.y);
            }
        }
        __syncthreads();

#pragma unroll
        for (int j = 0; j < 8; j++) {
            int r = ng*8 + j;
            int n = n0 + r;
            float4 u;
            if (n < NN) {
                float2 a0 = u2f(ai[j][0]), a1 = u2f(ai[j][1]);
                float2 o0 = u2f(ao[j][0]), o1 = u2f(ao[j][1]);
                u.x = (o0.x + obs[c4+0]) / (1.f + __expf(-(a0.x + ibs[c4+0])));
                u.y = (o0.y + obs[c4+1]) / (1.f + __expf(-(a0.y + ibs[c4+1])));
                u.z = (o1.x + obs[c4+2]) / (1.f + __expf(-(a1.x + ibs[c4+2])));
                u.w = (o1.y + obs[c4+3]) / (1.f + __expf(-(a1.y + ibs[c4+3])));
            } else {
                u = make_float4(0.f, 0.f, 0.f, 0.f);
            }
            *(float4*)&hs[r*CC + c4] = u;
        }
        __syncthreads();

#pragma unroll 2
        for (int n = 0; n < 128; n++) {
            ull u0 = dupf(hs[n*CC + kc2 + 0]);
            ull u1 = dupf(hs[n*CC + kc2 + 1]);
#pragma unroll
            for (int mp = 0; mp < 4; mp++) {
                ull phv = *(const ull*)&phis[n*MM + km8 + 2*mp];
                ffma2(kvacc[mp][0], phv, u0);
                ffma2(kvacc[mp][1], phv, u1);
            }
        }
    }

    float* kvb = &d_kv[((size_t)layer*BB + b)*(MM*CC)];
#pragma unroll
    for (int mp = 0; mp < 4; mp++) {
        float2 f0 = u2f(kvacc[mp][0]);
        float2 f1 = u2f(kvacc[mp][1]);
        int m0 = km8 + 2*mp;
        atomicAdd(&kvb[(m0+0)*CC + kc2 + 0], f0.x);
        atomicAdd(&kvb[(m0+1)*CC + kc2 + 0], f0.y);
        atomicAdd(&kvb[(m0+0)*CC + kc2 + 1], f1.x);
        atomicAdd(&kvb[(m0+1)*CC + kc2 + 1], f1.y);
    }
}

// ---------- num/den + residual + LN (f32x2), 32-node tiles (R13 layout) ----------
__global__ __launch_bounds__(256) void k_numln(int layer,
    const float* __restrict__ ln_g, const float* __restrict__ ln_b)
{
    extern __shared__ float kvs[];               // 32 KB dynamic (opted-in)
    __shared__ ull phis2[32*MM];
    __shared__ ull ksd[MM];
    __shared__ float lg[CC], lb[CC];
    int tid = threadIdx.x, b = blockIdx.y, chunk = blockIdx.x;
    for (int i = tid*4; i < MM*CC; i += 1024)
        *(float4*)&kvs[i] = *(const float4*)&d_kv[((size_t)layer*BB + b)*(MM*CC) + i];
    if (tid < MM) ksd[tid] = dupf(d_ksum[b*MM+tid]);
    if (tid < CC) { lg[tid] = ln_g[layer*CC+tid]; lb[tid] = ln_b[layer*CC+tid]; }
    __syncthreads();

    int cg = tid & 31, ng = tid >> 5;
    int c4 = cg*4;

    for (int t = 0; t < 16; t++) {
        int n0 = chunk*512 + t*32;
        if (n0 >= NN) break;
        __syncthreads();
        for (int i = tid; i < 512; i += 256) {
            int r = i >> 4, mq = (i & 15)*4;
            int n = n0 + r;
            float4 v = (n < NN) ? *(const float4*)&d_phiq[((size_t)b*NN+n)*MM + mq]
                                : make_float4(0.f,0.f,0.f,0.f);
            phis2[r*MM+mq+0] = dupf(v.x);
            phis2[r*MM+mq+1] = dupf(v.y);
            phis2[r*MM+mq+2] = dupf(v.z);
            phis2[r*MM+mq+3] = dupf(v.w);
        }
        __syncthreads();

        ull an[4][2], ad2[4];
#pragma unroll
        for (int j = 0; j < 4; j++) { an[j][0]=0ULL; an[j][1]=0ULL; ad2[j]=0ULL; }
#pragma unroll 2
        for (int m = 0; m < MM; m++) {
            ulonglong2 kf = *(const ulonglong2*)&kvs[m*CC + c4];
            ull ks = ksd[m];
#pragma unroll
            for (int j = 0; j < 4; j++) {
                ull pq = phis2[(ng*4+j)*MM + m];
                ffma2(an[j][0], pq, kf.x);
                ffma2(an[j][1], pq, kf.y);
                ffma2(ad2[j],   pq, ks);
            }
        }
#pragma unroll
        for (int j = 0; j < 4; j++) {
            int n = n0 + ng*4 + j;
            if (n >= NN) continue;   // warp-uniform
            size_t base = ((size_t)b*NN + n)*CC + c4;
            float4 hv = *(const float4*)&d_h[base];
            float2 n0f = u2f(an[j][0]), n1f = u2f(an[j][1]);
            float inv = 1.f / u2f(ad2[j]).x;
            float v0 = n0f.x*inv + hv.x;
            float v1 = n0f.y*inv + hv.y;
            float v2 = n1f.x*inv + hv.z;
            float v3 = n1f.y*inv + hv.w;
            float s1 = v0+v1+v2+v3;
            float s2 = v0*v0+v1*v1+v2*v2+v3*v3;
#pragma unroll
            for (int o = 16; o >= 1; o >>= 1) {
                s1 += __shfl_xor_sync(0xffffffffu, s1, o);
                s2 += __shfl_xor_sync(0xffffffffu, s2, o);
            }
            float mu = s1*(1.f/128.f);
            float var = s2*(1.f/128.f) - mu*mu;
            float rs = rsqrtf(var + 1e-5f);
            float4 o4;
            o4.x = (v0-mu)*rs*lg[c4+0] + lb[c4+0];
            o4.y = (v1-mu)*rs*lg[c4+1] + lb[c4+1];
            o4.z = (v2-mu)*rs*lg[c4+2] + lb[c4+2];
            o4.w = (v3-mu)*rs*lg[c4+3] + lb[c4+3];
            *(float4*)&d_h[base] = o4;
        }
    }
}

// ------------------------- final regression (packed f32x2) -----------------------
__global__ __launch_bounds__(256) void k_out(
    const float* __restrict__ reg_w, const float* __restrict__ reg_b,
    float* __restrict__ out)
{
    __shared__ __align__(8) float rw2s[PP*CC];
    __shared__ float rbs[PP];
    int tid = threadIdx.x, b = blockIdx.y;
    for (int i = tid; i < PP*CC; i += 256) {
        int p = i >> 7, c = i & 127;
        rw2s[i] = reg_w[p*(2*CC) + CC + c];
    }
    if (tid < PP) rbs[tid] = reg_b[tid];
    __syncthreads();
    int n = blockIdx.x*256 + tid;
    if (n >= NN) return;
    ull ap[PP];
#pragma unroll
    for (int p = 0; p < PP; p++) ap[p] = 0ULL;
    size_t hb = ((size_t)b*NN + n)*CC;
#pragma unroll 4
    for (int q = 0; q < CC/4; q++) {
        ulonglong2 hv = *(const ulonglong2*)&d_h[hb + q*4];
#pragma unroll
        for (int p = 0; p < PP; p++) {
            ffma2(ap[p], hv.x, *(const ull*)&rw2s[p*CC + q*4]);
            ffma2(ap[p], hv.y, *(const ull*)&rw2s[p*CC + q*4 + 2]);
        }
    }
    size_t sb = ((size_t)b*NN + n)*PP;
#pragma unroll
    for (int p = 0; p < PP; p++) {
        float2 f = u2f(ap[p]);
        out[(b*PP + p)*NN + n] = d_skip[sb + p] + rbs[p] + f.x + f.y;
    }
}

// ------------------------- launch ------------------------------------------------
extern "C" void kernel_launch(void* const* d_in, const int* in_sizes, int n_in,
                              void* d_out, int out_size)
{
    const float* x        = (const float*)d_in[0];
    const float* x_mark   = (const float*)d_in[1];
    const float* node_emb = (const float*)d_in[2];
    const float* time_tab = (const float*)d_in[3];
    const float* week_tab = (const float*)d_in[4];
    const float* input_w  = (const float*)d_in[5];
    const float* input_b  = (const float*)d_in[6];
    const float* w1_w     = (const float*)d_in[7];
    const float* w1_b     = (const float*)d_in[8];
    const float* w2_w     = (const float*)d_in[9];
    const float* w2_b     = (const float*)d_in[10];
    const float* in_w     = (const float*)d_in[11];
    const float* in_b     = (const float*)d_in[12];
    const float* out_w    = (const float*)d_in[13];
    const float* out_b    = (const float*)d_in[14];
    const float* ln_g     = (const float*)d_in[15];
    const float* ln_b     = (const float*)d_in[16];
    const float* reg_w    = (const float*)d_in[17];
    const float* reg_b    = (const float*)d_in[18];
    const float* proj     = (const float*)d_in[19];
    float* out = (float*)d_out;

    cudaFuncSetAttribute(k_gate0,  cudaFuncAttributeMaxDynamicSharedMemorySize, G0_SMEM);
    cudaFuncSetAttribute(k_gatekv, cudaFuncAttributeMaxDynamicSharedMemorySize, GK_SMEM);
    cudaFuncSetAttribute(k_numln,  cudaFuncAttributeMaxDynamicSharedMemorySize, 32768);

    k_batch<<<1, 256>>>(x_mark, time_tab, week_tab, w1_w, w1_b, w2_w, w2_b,
                        input_w, input_b, proj, reg_w, in_w, out_w);
    k_node<<<(NN+127)/128, 128>>>(node_emb, w1_w, w2_w, proj, in_w, out_w);
    k_embed<<<dim3((NN+255)/256, BB), 256>>>(x, node_emb, input_w, reg_w);
    // layer-0 fused gate+kv is the 4th launch -> profiled by ncu
    k_gate0<<<dim3(GX, BB), 512, G0_SMEM>>>(in_w, in_b, out_w, out_b);
    k_ksum<<<dim3((NN+255)/256, BB), 256>>>();
    k_numln<<<dim3(40, BB), 256, 32768>>>(0, ln_g, ln_b);
    for (int l = 1; l < 3; l++) {
        k_gatekv<<<dim3(GX, BB), 512, GK_SMEM>>>(l, in_w, in_b, out_w, out_b);
        k_numln<<<dim3(40, BB), 256, 32768>>>(l, ln_g, ln_b);
    }
    k_out<<<dim3((NN+255)/256, BB), 256>>>(reg_w, reg_b, out);
}